// round 1
// baseline (speedup 1.0000x reference)
#include <cuda_runtime.h>
#include <cstdint>

// ---------------------------------------------------------------------------
// WLSMLPLayer: h = MLP(X) [3-layer, ReLU, fp32 weights], agg[d] = sum h[src],
// out = concat([h, agg]).  tf32 mma.sync GEMMs + atomic edge aggregation.
// ---------------------------------------------------------------------------

#define BM 128
#define BN 128
#define BK 32
#define NTHREADS 256

// Scratch (device globals: allocation-free rule)
__device__ float g_h1[100000 * 256];
__device__ float g_h2[100000 * 512];
__device__ float g_h [100000 * 128];
__device__ int   g_is64;

__device__ __forceinline__ unsigned f2tf32(float x) {
    unsigned u;
    asm("cvt.rna.tf32.f32 %0, %1;" : "=r"(u) : "f"(x));
    return u;
}

// C[M,N] = act(A[M,K] @ B[K,N] + bias). B row-major (fan_in x fan_out).
// DUAL: additionally write result into out2[:, 0:128] (stride 256) and zero
// out2[:, 128:256] (agg region init, overwritten later by atomics).
template <bool RELU, bool DUAL>
__global__ __launch_bounds__(NTHREADS, 2)
void gemm_bias_kernel(const float* __restrict__ A, const float* __restrict__ B,
                      const float* __restrict__ bias, float* __restrict__ C,
                      float* __restrict__ out2, int M, int K, int N)
{
    __shared__ __align__(16) float As[BM][BK + 4];   // stride 36: conflict-free frags
    __shared__ __align__(16) float Bs[BK][BN + 4];   // stride 132

    const int tid  = threadIdx.x;
    const int wid  = tid >> 5, lane = tid & 31;
    const int wm   = wid >> 2;          // 0..1 : 64 rows each
    const int wn   = wid & 3;           // 0..3 : 32 cols each
    const int gid  = lane >> 2;         // 0..7
    const int tig  = lane & 3;          // 0..3
    const int bm0  = blockIdx.y * BM;
    const int bn0  = blockIdx.x * BN;

    // global->reg load mapping
    const int arow = tid >> 3;          // 0..31 (x4 via i*32)
    const int acol = (tid & 7) * 4;     // 0..28
    const int brow = tid >> 5;          // 0..7  (x4 via i*8)
    const int bcol = lane * 4;          // 0..124

    float4 ra[4], rb[4];

    auto loadG = [&](int kk) {
#pragma unroll
        for (int i = 0; i < 4; i++) {
            int r = bm0 + arow + 32 * i;
            if (r < M)
                ra[i] = *reinterpret_cast<const float4*>(A + (size_t)r * K + kk + acol);
            else
                ra[i] = make_float4(0.f, 0.f, 0.f, 0.f);
        }
#pragma unroll
        for (int i = 0; i < 4; i++)
            rb[i] = *reinterpret_cast<const float4*>(B + (size_t)(kk + brow + 8 * i) * N + bn0 + bcol);
    };

    auto storeS = [&]() {
#pragma unroll
        for (int i = 0; i < 4; i++) {
            int r = arow + 32 * i;
            float4 v;
            v.x = __uint_as_float(f2tf32(ra[i].x));
            v.y = __uint_as_float(f2tf32(ra[i].y));
            v.z = __uint_as_float(f2tf32(ra[i].z));
            v.w = __uint_as_float(f2tf32(ra[i].w));
            *reinterpret_cast<float4*>(&As[r][acol]) = v;
        }
#pragma unroll
        for (int i = 0; i < 4; i++) {
            int r = brow + 8 * i;
            float4 v;
            v.x = __uint_as_float(f2tf32(rb[i].x));
            v.y = __uint_as_float(f2tf32(rb[i].y));
            v.z = __uint_as_float(f2tf32(rb[i].z));
            v.w = __uint_as_float(f2tf32(rb[i].w));
            *reinterpret_cast<float4*>(&Bs[r][bcol]) = v;
        }
    };

    float acc[4][4][4];
#pragma unroll
    for (int a = 0; a < 4; a++)
#pragma unroll
        for (int b = 0; b < 4; b++)
#pragma unroll
            for (int c = 0; c < 4; c++) acc[a][b][c] = 0.f;

    loadG(0);
    storeS();
    __syncthreads();

    const int KT = K / BK;
    for (int kt = 0; kt < KT; ++kt) {
        if (kt + 1 < KT) loadG((kt + 1) * BK);   // prefetch next tile into regs

#pragma unroll
        for (int ks = 0; ks < BK / 8; ++ks) {
            const int k0 = ks * 8;
            unsigned af[4][4], bf[4][2];
#pragma unroll
            for (int mt = 0; mt < 4; ++mt) {
                int r = wm * 64 + mt * 16 + gid;
                af[mt][0] = __float_as_uint(As[r    ][k0 + tig    ]);
                af[mt][1] = __float_as_uint(As[r + 8][k0 + tig    ]);
                af[mt][2] = __float_as_uint(As[r    ][k0 + tig + 4]);
                af[mt][3] = __float_as_uint(As[r + 8][k0 + tig + 4]);
            }
#pragma unroll
            for (int nt = 0; nt < 4; ++nt) {
                int c = wn * 32 + nt * 8 + gid;
                bf[nt][0] = __float_as_uint(Bs[k0 + tig    ][c]);
                bf[nt][1] = __float_as_uint(Bs[k0 + tig + 4][c]);
            }
#pragma unroll
            for (int mt = 0; mt < 4; ++mt)
#pragma unroll
                for (int nt = 0; nt < 4; ++nt)
                    asm volatile(
                        "mma.sync.aligned.m16n8k8.row.col.f32.tf32.tf32.f32 "
                        "{%0,%1,%2,%3}, {%4,%5,%6,%7}, {%8,%9}, {%0,%1,%2,%3};"
                        : "+f"(acc[mt][nt][0]), "+f"(acc[mt][nt][1]),
                          "+f"(acc[mt][nt][2]), "+f"(acc[mt][nt][3])
                        : "r"(af[mt][0]), "r"(af[mt][1]), "r"(af[mt][2]), "r"(af[mt][3]),
                          "r"(bf[nt][0]), "r"(bf[nt][1]));
        }
        __syncthreads();
        if (kt + 1 < KT) {
            storeS();
            __syncthreads();
        }
    }

    // epilogue: bias (+ReLU), store; DUAL also mirrors into out2 and zeros agg
#pragma unroll
    for (int mt = 0; mt < 4; ++mt) {
#pragma unroll
        for (int nt = 0; nt < 4; ++nt) {
            int c = bn0 + wn * 32 + nt * 8 + 2 * tig;
            float bv0 = bias[c], bv1 = bias[c + 1];
#pragma unroll
            for (int hh = 0; hh < 2; ++hh) {
                int r = bm0 + wm * 64 + mt * 16 + gid + hh * 8;
                if (r < M) {
                    float v0 = acc[mt][nt][hh * 2 + 0] + bv0;
                    float v1 = acc[mt][nt][hh * 2 + 1] + bv1;
                    if (RELU) { v0 = fmaxf(v0, 0.f); v1 = fmaxf(v1, 0.f); }
                    C[(size_t)r * N + c    ] = v0;
                    C[(size_t)r * N + c + 1] = v1;
                    if (DUAL) {
                        float* orow = out2 + (size_t)r * 256;
                        orow[c      ] = v0;
                        orow[c + 1  ] = v1;
                        orow[128 + c    ] = 0.f;   // init agg region
                        orow[128 + c + 1] = 0.f;
                    }
                }
            }
        }
    }
}

// Sniff whether index arrays are int64 or int32 (JAX x64-off silently demotes).
// For nonneg node ids < 2^31: int64 => all odd 32-bit words zero.
__global__ void detect_kernel(const unsigned* __restrict__ w) {
    if (threadIdx.x == 0 && blockIdx.x == 0) {
        int ok = 1;
        for (int i = 1; i < 256; i += 2) ok &= (w[i] == 0u);
        g_is64 = ok;
    }
}

// One warp per edge: gather h[src] (512B, L2-resident) and atomically add into
// out[dst, 128:256].
__global__ void edge_kernel(const void* __restrict__ srcp, const void* __restrict__ dstp,
                            const float* __restrict__ h, float* __restrict__ out, int E)
{
    int gw   = (int)((blockIdx.x * (unsigned)blockDim.x + threadIdx.x) >> 5);
    int lane = threadIdx.x & 31;
    if (gw >= E) return;

    long long s, d;
    if (g_is64) {
        s = ((const long long*)srcp)[gw];
        d = ((const long long*)dstp)[gw];
    } else {
        s = ((const int*)srcp)[gw];
        d = ((const int*)dstp)[gw];
    }

    float4 v = *reinterpret_cast<const float4*>(h + s * 128 + lane * 4);
    float* o = out + d * 256 + 128 + lane * 4;
    atomicAdd(o + 0, v.x);
    atomicAdd(o + 1, v.y);
    atomicAdd(o + 2, v.z);
    atomicAdd(o + 3, v.w);
}

extern "C" void kernel_launch(void* const* d_in, const int* in_sizes, int n_in,
                              void* d_out, int out_size)
{
    const float* X   = (const float*)d_in[0];
    const void*  src = d_in[1];
    const void*  dst = d_in[2];
    const float* W1  = (const float*)d_in[3];
    const float* b1  = (const float*)d_in[4];
    const float* W2  = (const float*)d_in[5];
    const float* b2  = (const float*)d_in[6];
    const float* W3  = (const float*)d_in[7];
    const float* b3  = (const float*)d_in[8];
    float* out = (float*)d_out;

    const int N1 = in_sizes[4];          // 256
    const int N2 = in_sizes[6];          // 512
    const int N3 = in_sizes[8];          // 128
    const int K1 = in_sizes[3] / N1;     // 128
    const int M  = in_sizes[0] / K1;     // 100000
    const int E  = in_sizes[1];          // 3200000

    float *h1, *h2, *h;
    cudaGetSymbolAddress((void**)&h1, g_h1);
    cudaGetSymbolAddress((void**)&h2, g_h2);
    cudaGetSymbolAddress((void**)&h,  g_h);

    const int MT = (M + BM - 1) / BM;

    detect_kernel<<<1, 1>>>((const unsigned*)src);

    gemm_bias_kernel<true,  false><<<dim3(N1 / BN, MT), NTHREADS>>>(X,  W1, b1, h1, nullptr, M, K1, N1);
    gemm_bias_kernel<true,  false><<<dim3(N2 / BN, MT), NTHREADS>>>(h1, W2, b2, h2, nullptr, M, N1, N2);
    gemm_bias_kernel<false, true ><<<dim3(N3 / BN, MT), NTHREADS>>>(h2, W3, b3, h,  out,     M, N2, N3);

    const int blocks = (E + 7) / 8;      // 8 warps per 256-thread block, 1 edge/warp
    edge_kernel<<<blocks, NTHREADS>>>(src, dst, h, out, E);
}

// round 2
// speedup vs baseline: 1.5995x; 1.5995x over previous
#include <cuda_runtime.h>
#include <cstdint>

// ---------------------------------------------------------------------------
// WLSMLPLayer: h = MLP(X) [3-layer, ReLU, fp32], agg[d] = sum h[src],
// out = concat([h, agg]).
// R2: cp.async double-buffered tf32 GEMM + red.global.add.v4.f32 edge phase.
// ---------------------------------------------------------------------------

#define BM 128
#define BN 128
#define BK 32
#define NTHREADS 256

#define AS_STRIDE 36            // BK + 4 pad (conflict-free frag loads)
#define BS_STRIDE 132           // BN + 4 pad
#define A_STAGE   (BM * AS_STRIDE)          // 4608 floats
#define B_STAGE   (BK * BS_STRIDE)          // 4224 floats
#define STAGE     (A_STAGE + B_STAGE)       // 8832 floats
#define SMEM_BYTES (2 * STAGE * 4)          // 70656 B

// Scratch (device globals: allocation-free rule)
__device__ float g_h1[100000 * 256];
__device__ float g_h2[100000 * 512];
__device__ float g_h [100000 * 128];
__device__ int   g_is64;

__device__ __forceinline__ unsigned f2tf32(float x) {
    unsigned u;
    asm("cvt.rna.tf32.f32 %0, %1;" : "=r"(u) : "f"(x));
    return u;
}

__device__ __forceinline__ void cp16(float* smem_dst, const float* gmem_src, int valid_bytes) {
    unsigned s = (unsigned)__cvta_generic_to_shared(smem_dst);
    asm volatile("cp.async.cg.shared.global [%0], [%1], 16, %2;"
                 :: "r"(s), "l"(gmem_src), "r"(valid_bytes));
}
__device__ __forceinline__ void cp_commit() {
    asm volatile("cp.async.commit_group;");
}
template <int N>
__device__ __forceinline__ void cp_wait() {
    asm volatile("cp.async.wait_group %0;" :: "n"(N));
}

// C[M,N] = act(A[M,K] @ B[K,N] + bias). B row-major (fan_in x fan_out).
// DUAL: additionally write result into out2[:, 0:128] (stride 256) and zero
// out2[:, 128:256] (agg region init, accumulated later by red ops).
template <bool RELU, bool DUAL>
__global__ __launch_bounds__(NTHREADS, 2)
void gemm_bias_kernel(const float* __restrict__ A, const float* __restrict__ B,
                      const float* __restrict__ bias, float* __restrict__ C,
                      float* __restrict__ out2, int M, int K, int N)
{
    extern __shared__ __align__(16) float smem[];

    const int tid  = threadIdx.x;
    const int wid  = tid >> 5, lane = tid & 31;
    const int wm   = wid >> 2;          // 0..1 : 64 rows each
    const int wn   = wid & 3;           // 0..3 : 32 cols each
    const int gid  = lane >> 2;         // 0..7
    const int tig  = lane & 3;          // 0..3
    const int bm0  = blockIdx.y * BM;
    const int bn0  = blockIdx.x * BN;

    // global->smem async-copy mapping (4 x 16B chunks each for A and B)
    const int arow = tid >> 3;          // 0..31 (x4 via i*32)
    const int acol = (tid & 7) * 4;     // 0..28
    const int brow = tid >> 5;          // 0..7  (x4 via i*8)
    const int bcol = lane * 4;          // 0..124

    auto issue = [&](int kk, int stage) {
        float* As = smem + stage * STAGE;
        float* Bs = As + A_STAGE;
#pragma unroll
        for (int i = 0; i < 4; i++) {
            int r  = bm0 + arow + 32 * i;
            int ok = (r < M) ? 16 : 0;
            const float* src = A + (size_t)(ok ? r : 0) * K + kk + acol;
            cp16(As + (arow + 32 * i) * AS_STRIDE + acol, src, ok);
        }
#pragma unroll
        for (int i = 0; i < 4; i++) {
            int r = brow + 8 * i;
            cp16(Bs + r * BS_STRIDE + bcol,
                 B + (size_t)(kk + r) * N + bn0 + bcol, 16);
        }
        cp_commit();
    };

    float acc[4][4][4];
#pragma unroll
    for (int a = 0; a < 4; a++)
#pragma unroll
        for (int b = 0; b < 4; b++)
#pragma unroll
            for (int c = 0; c < 4; c++) acc[a][b][c] = 0.f;

    const int KT = K / BK;
    issue(0, 0);

    for (int kt = 0; kt < KT; ++kt) {
        if (kt + 1 < KT) {
            issue((kt + 1) * BK, (kt + 1) & 1);
            cp_wait<1>();
        } else {
            cp_wait<0>();
        }
        __syncthreads();

        const float* As = smem + (kt & 1) * STAGE;
        const float* Bs = As + A_STAGE;

#pragma unroll
        for (int ks = 0; ks < BK / 8; ++ks) {
            const int k0 = ks * 8;
            unsigned af[4][4], bf[4][2];
#pragma unroll
            for (int mt = 0; mt < 4; ++mt) {
                int r = wm * 64 + mt * 16 + gid;
                af[mt][0] = f2tf32(As[(r    ) * AS_STRIDE + k0 + tig    ]);
                af[mt][1] = f2tf32(As[(r + 8) * AS_STRIDE + k0 + tig    ]);
                af[mt][2] = f2tf32(As[(r    ) * AS_STRIDE + k0 + tig + 4]);
                af[mt][3] = f2tf32(As[(r + 8) * AS_STRIDE + k0 + tig + 4]);
            }
#pragma unroll
            for (int nt = 0; nt < 4; ++nt) {
                int c = wn * 32 + nt * 8 + gid;
                bf[nt][0] = f2tf32(Bs[(k0 + tig    ) * BS_STRIDE + c]);
                bf[nt][1] = f2tf32(Bs[(k0 + tig + 4) * BS_STRIDE + c]);
            }
#pragma unroll
            for (int mt = 0; mt < 4; ++mt)
#pragma unroll
                for (int nt = 0; nt < 4; ++nt)
                    asm volatile(
                        "mma.sync.aligned.m16n8k8.row.col.f32.tf32.tf32.f32 "
                        "{%0,%1,%2,%3}, {%4,%5,%6,%7}, {%8,%9}, {%0,%1,%2,%3};"
                        : "+f"(acc[mt][nt][0]), "+f"(acc[mt][nt][1]),
                          "+f"(acc[mt][nt][2]), "+f"(acc[mt][nt][3])
                        : "r"(af[mt][0]), "r"(af[mt][1]), "r"(af[mt][2]), "r"(af[mt][3]),
                          "r"(bf[nt][0]), "r"(bf[nt][1]));
        }
        __syncthreads();
    }

    // epilogue: bias (+ReLU), store; DUAL also mirrors into out2 and zeros agg
#pragma unroll
    for (int mt = 0; mt < 4; ++mt) {
#pragma unroll
        for (int nt = 0; nt < 4; ++nt) {
            int c = bn0 + wn * 32 + nt * 8 + 2 * tig;
            float bv0 = bias[c], bv1 = bias[c + 1];
#pragma unroll
            for (int hh = 0; hh < 2; ++hh) {
                int r = bm0 + wm * 64 + mt * 16 + gid + hh * 8;
                if (r < M) {
                    float v0 = acc[mt][nt][hh * 2 + 0] + bv0;
                    float v1 = acc[mt][nt][hh * 2 + 1] + bv1;
                    if (RELU) { v0 = fmaxf(v0, 0.f); v1 = fmaxf(v1, 0.f); }
                    C[(size_t)r * N + c    ] = v0;
                    C[(size_t)r * N + c + 1] = v1;
                    if (DUAL) {
                        float* orow = out2 + (size_t)r * 256;
                        orow[c      ] = v0;
                        orow[c + 1  ] = v1;
                        orow[128 + c    ] = 0.f;   // init agg region
                        orow[128 + c + 1] = 0.f;
                    }
                }
            }
        }
    }
}

// Sniff whether index arrays are int64 or int32 (JAX x64-off silently demotes).
// For nonneg node ids < 2^31: int64 => all odd 32-bit words zero.
__global__ void detect_kernel(const unsigned* __restrict__ w) {
    if (threadIdx.x == 0 && blockIdx.x == 0) {
        int ok = 1;
        for (int i = 1; i < 256; i += 2) ok &= (w[i] == 0u);
        g_is64 = ok;
    }
}

// One warp per edge: gather h[src] (512B, L2-resident) and vector-reduce into
// out[dst, 128:256] with a single 16B red op per lane.
__global__ void edge_kernel(const void* __restrict__ srcp, const void* __restrict__ dstp,
                            const float* __restrict__ h, float* __restrict__ out, int E)
{
    int gw   = (int)((blockIdx.x * (unsigned)blockDim.x + threadIdx.x) >> 5);
    int lane = threadIdx.x & 31;
    if (gw >= E) return;

    long long s, d;
    if (g_is64) {
        s = ((const long long*)srcp)[gw];
        d = ((const long long*)dstp)[gw];
    } else {
        s = ((const int*)srcp)[gw];
        d = ((const int*)dstp)[gw];
    }

    float4 v = *reinterpret_cast<const float4*>(h + s * 128 + lane * 4);
    float* o = out + d * 256 + 128 + lane * 4;
    asm volatile("red.relaxed.gpu.global.add.v4.f32 [%0], {%1,%2,%3,%4};"
                 :: "l"(o), "f"(v.x), "f"(v.y), "f"(v.z), "f"(v.w)
                 : "memory");
}

extern "C" void kernel_launch(void* const* d_in, const int* in_sizes, int n_in,
                              void* d_out, int out_size)
{
    const float* X   = (const float*)d_in[0];
    const void*  src = d_in[1];
    const void*  dst = d_in[2];
    const float* W1  = (const float*)d_in[3];
    const float* b1  = (const float*)d_in[4];
    const float* W2  = (const float*)d_in[5];
    const float* b2  = (const float*)d_in[6];
    const float* W3  = (const float*)d_in[7];
    const float* b3  = (const float*)d_in[8];
    float* out = (float*)d_out;

    const int N1 = in_sizes[4];          // 256
    const int N2 = in_sizes[6];          // 512
    const int N3 = in_sizes[8];          // 128
    const int K1 = in_sizes[3] / N1;     // 128
    const int M  = in_sizes[0] / K1;     // 100000
    const int E  = in_sizes[1];          // 3200000

    float *h1, *h2, *h;
    cudaGetSymbolAddress((void**)&h1, g_h1);
    cudaGetSymbolAddress((void**)&h2, g_h2);
    cudaGetSymbolAddress((void**)&h,  g_h);

    cudaFuncSetAttribute(gemm_bias_kernel<true,  false>,
                         cudaFuncAttributeMaxDynamicSharedMemorySize, SMEM_BYTES);
    cudaFuncSetAttribute(gemm_bias_kernel<false, true>,
                         cudaFuncAttributeMaxDynamicSharedMemorySize, SMEM_BYTES);

    const int MT = (M + BM - 1) / BM;

    detect_kernel<<<1, 1>>>((const unsigned*)src);

    gemm_bias_kernel<true,  false><<<dim3(N1 / BN, MT), NTHREADS, SMEM_BYTES>>>(X,  W1, b1, h1, nullptr, M, K1, N1);
    gemm_bias_kernel<true,  false><<<dim3(N2 / BN, MT), NTHREADS, SMEM_BYTES>>>(h1, W2, b2, h2, nullptr, M, N1, N2);
    gemm_bias_kernel<false, true ><<<dim3(N3 / BN, MT), NTHREADS, SMEM_BYTES>>>(h2, W3, b3, h,  out,     M, N2, N3);

    const int blocks = (E + 7) / 8;      // 8 warps per 256-thread block, 1 edge/warp
    edge_kernel<<<blocks, NTHREADS>>>(src, dst, h, out, E);
}

// round 3
// speedup vs baseline: 2.2153x; 1.3850x over previous
#include <cuda_runtime.h>
#include <cuda_fp16.h>
#include <cstdint>

// ---------------------------------------------------------------------------
// WLSMLPLayer: h = MLP(X) [3-layer, ReLU], agg[d] = sum h[src],
// out = concat([h, agg]).
// R3: fp16 m16n8k16 mma + ldmatrix + cp.async double-buffer; fp16 gather.
// ---------------------------------------------------------------------------

#define BM 128
#define BN 128
#define BK 32
#define NTHREADS 256

#define AS_STRIDE 40                 // halves per A smem row (32 + 8 pad -> 80B)
#define BS_STRIDE 136                // halves per B smem row (128 + 8 pad -> 272B)
#define A_STAGE   (BM * AS_STRIDE)   // 5120 halves
#define B_STAGE   (BK * BS_STRIDE)   // 4352 halves
#define STAGE     (A_STAGE + B_STAGE)

// Scratch (device globals: allocation-free rule)
__device__ __half g_xh[100000 * 128];
__device__ __half g_h1[100000 * 256];
__device__ __half g_h2[100000 * 512];
__device__ __half g_hh[100000 * 128];   // fp16 copy of h for edge gather
__device__ __half g_w1[128 * 256];
__device__ __half g_w2[256 * 512];
__device__ __half g_w3[512 * 128];
__device__ int    g_is64;

__device__ __forceinline__ void cp16(__half* smem_dst, const __half* gmem_src, int valid_bytes) {
    unsigned s = (unsigned)__cvta_generic_to_shared(smem_dst);
    asm volatile("cp.async.cg.shared.global [%0], [%1], 16, %2;"
                 :: "r"(s), "l"(gmem_src), "r"(valid_bytes));
}
__device__ __forceinline__ void cp_commit() { asm volatile("cp.async.commit_group;"); }
template <int N>
__device__ __forceinline__ void cp_wait() { asm volatile("cp.async.wait_group %0;" :: "n"(N)); }

// C[M,N] = act(A[M,K] @ B[K,N] + bias), A/B/C half, accum fp32.
// DUAL: also write fp32 result into out2[:,0:128] (stride 256) and zero
// out2[:,128:256] (agg init, accumulated later by red ops).
template <bool RELU, bool DUAL>
__global__ __launch_bounds__(NTHREADS, 2)
void gemm_bias_kernel(const __half* __restrict__ A, const __half* __restrict__ B,
                      const float* __restrict__ bias, __half* __restrict__ C,
                      float* __restrict__ out2, int M, int K, int N)
{
    __shared__ __align__(16) __half smem[2 * STAGE];

    const int tid  = threadIdx.x;
    const int wid  = tid >> 5, lane = tid & 31;
    const int wm   = wid >> 2;          // 0..1 : 64 rows each
    const int wn   = wid & 3;           // 0..3 : 32 cols each
    const int gid  = lane >> 2;         // 0..7
    const int tig  = lane & 3;          // 0..3
    const int bm0  = blockIdx.y * BM;
    const int bn0  = blockIdx.x * BN;

    const unsigned sbase = (unsigned)__cvta_generic_to_shared(smem);

    // ldmatrix lane address components
    const int a_r  = (lane & 7) + ((lane >> 3) & 1) * 8;   // row within 16
    const int a_k  = ((lane >> 4) & 1) * 8;                // k offset 0/8
    const int b_k  = (lane & 7) + ((lane >> 3) & 1) * 8;   // k within 16
    const int b_n  = ((lane >> 4) & 1) * 8;                // n offset 0/8

    auto issue = [&](int kk, int stage) {
        __half* As = smem + stage * STAGE;
        __half* Bs = As + A_STAGE;
        // A tile 128x32 halves: 512 16B-chunks; 2 per thread
#pragma unroll
        for (int i = 0; i < 2; i++) {
            int c   = tid + 256 * i;
            int row = c >> 2, col = (c & 3) * 8;
            int r   = bm0 + row;
            int ok  = (r < M) ? 16 : 0;
            cp16(As + row * AS_STRIDE + col,
                 A + (size_t)(ok ? r : 0) * K + kk + col, ok);
        }
        // B tile 32x128 halves: 512 chunks; 2 per thread
#pragma unroll
        for (int i = 0; i < 2; i++) {
            int c   = tid + 256 * i;
            int row = c >> 4, col = (c & 15) * 8;
            cp16(Bs + row * BS_STRIDE + col,
                 B + (size_t)(kk + row) * N + bn0 + col, 16);
        }
        cp_commit();
    };

    float acc[4][4][4];
#pragma unroll
    for (int a = 0; a < 4; a++)
#pragma unroll
        for (int b = 0; b < 4; b++)
#pragma unroll
            for (int c = 0; c < 4; c++) acc[a][b][c] = 0.f;

    const int KT = K / BK;
    issue(0, 0);

    for (int kt = 0; kt < KT; ++kt) {
        if (kt + 1 < KT) { issue((kt + 1) * BK, (kt + 1) & 1); cp_wait<1>(); }
        else             { cp_wait<0>(); }
        __syncthreads();

        const unsigned as0 = sbase + ((kt & 1) * STAGE) * 2;
        const unsigned bs0 = as0 + A_STAGE * 2;

#pragma unroll
        for (int ks = 0; ks < 2; ++ks) {     // two k16 steps per BK=32
            const int k0 = ks * 16;
            unsigned af[4][4], bf[4][2];
#pragma unroll
            for (int mt = 0; mt < 4; ++mt) {
                unsigned addr = as0 + ((wm * 64 + mt * 16 + a_r) * AS_STRIDE + k0 + a_k) * 2;
                asm volatile("ldmatrix.sync.aligned.m8n8.x4.shared.b16 {%0,%1,%2,%3}, [%4];"
                             : "=r"(af[mt][0]), "=r"(af[mt][1]), "=r"(af[mt][2]), "=r"(af[mt][3])
                             : "r"(addr));
            }
#pragma unroll
            for (int np = 0; np < 2; ++np) { // each covers 2 n8-tiles
                unsigned addr = bs0 + ((k0 + b_k) * BS_STRIDE + wn * 32 + np * 16 + b_n) * 2;
                asm volatile("ldmatrix.sync.aligned.m8n8.x4.trans.shared.b16 {%0,%1,%2,%3}, [%4];"
                             : "=r"(bf[2 * np][0]), "=r"(bf[2 * np][1]),
                               "=r"(bf[2 * np + 1][0]), "=r"(bf[2 * np + 1][1])
                             : "r"(addr));
            }
#pragma unroll
            for (int mt = 0; mt < 4; ++mt)
#pragma unroll
                for (int nt = 0; nt < 4; ++nt)
                    asm volatile(
                        "mma.sync.aligned.m16n8k16.row.col.f32.f16.f16.f32 "
                        "{%0,%1,%2,%3}, {%4,%5,%6,%7}, {%8,%9}, {%0,%1,%2,%3};"
                        : "+f"(acc[mt][nt][0]), "+f"(acc[mt][nt][1]),
                          "+f"(acc[mt][nt][2]), "+f"(acc[mt][nt][3])
                        : "r"(af[mt][0]), "r"(af[mt][1]), "r"(af[mt][2]), "r"(af[mt][3]),
                          "r"(bf[nt][0]), "r"(bf[nt][1]));
        }
        __syncthreads();
    }

    // epilogue: bias (+ReLU); store half C; DUAL also fp32 out + agg zero-init
#pragma unroll
    for (int mt = 0; mt < 4; ++mt) {
#pragma unroll
        for (int nt = 0; nt < 4; ++nt) {
            int c = bn0 + wn * 32 + nt * 8 + 2 * tig;
            float bv0 = bias[c], bv1 = bias[c + 1];
#pragma unroll
            for (int hh = 0; hh < 2; ++hh) {
                int r = bm0 + wm * 64 + mt * 16 + gid + hh * 8;
                if (r < M) {
                    float v0 = acc[mt][nt][hh * 2 + 0] + bv0;
                    float v1 = acc[mt][nt][hh * 2 + 1] + bv1;
                    if (RELU) { v0 = fmaxf(v0, 0.f); v1 = fmaxf(v1, 0.f); }
                    *reinterpret_cast<__half2*>(C + (size_t)r * N + c) =
                        __floats2half2_rn(v0, v1);
                    if (DUAL) {
                        float* orow = out2 + (size_t)r * 256;
                        orow[c      ] = v0;
                        orow[c + 1  ] = v1;
                        orow[128 + c    ] = 0.f;
                        orow[128 + c + 1] = 0.f;
                    }
                }
            }
        }
    }
}

// fp32 -> fp16 conversion (n multiple of 4)
__global__ void f2h_kernel(const float* __restrict__ in, __half* __restrict__ out, int n) {
    int idx = (blockIdx.x * blockDim.x + threadIdx.x) * 4;
    if (idx < n) {
        float4 v = *reinterpret_cast<const float4*>(in + idx);
        __half2* o = reinterpret_cast<__half2*>(out + idx);
        o[0] = __floats2half2_rn(v.x, v.y);
        o[1] = __floats2half2_rn(v.z, v.w);
    }
}

// Sniff int64 vs int32 indices (JAX x64-off silently demotes).
__global__ void detect_kernel(const unsigned* __restrict__ w) {
    if (threadIdx.x == 0 && blockIdx.x == 0) {
        int ok = 1;
        for (int i = 1; i < 256; i += 2) ok &= (w[i] == 0u);
        g_is64 = ok;
    }
}

// One warp per edge: gather hh[src] (256B fp16, L2-resident), convert, and
// vector-reduce fp32 into out[dst, 128:256].
__global__ void edge_kernel(const void* __restrict__ srcp, const void* __restrict__ dstp,
                            const __half* __restrict__ hh, float* __restrict__ out, int E)
{
    int gw   = (int)((blockIdx.x * (unsigned)blockDim.x + threadIdx.x) >> 5);
    int lane = threadIdx.x & 31;
    if (gw >= E) return;

    long long s, d;
    if (g_is64) {
        s = ((const long long*)srcp)[gw];
        d = ((const long long*)dstp)[gw];
    } else {
        s = ((const int*)srcp)[gw];
        d = ((const int*)dstp)[gw];
    }

    uint2 raw = *reinterpret_cast<const uint2*>(hh + s * 128 + lane * 4);
    __half2 p0 = *reinterpret_cast<__half2*>(&raw.x);
    __half2 p1 = *reinterpret_cast<__half2*>(&raw.y);
    float2 f0 = __half22float2(p0);
    float2 f1 = __half22float2(p1);

    float* o = out + d * 256 + 128 + lane * 4;
    asm volatile("red.relaxed.gpu.global.add.v4.f32 [%0], {%1,%2,%3,%4};"
                 :: "l"(o), "f"(f0.x), "f"(f0.y), "f"(f1.x), "f"(f1.y)
                 : "memory");
}

extern "C" void kernel_launch(void* const* d_in, const int* in_sizes, int n_in,
                              void* d_out, int out_size)
{
    const float* X   = (const float*)d_in[0];
    const void*  src = d_in[1];
    const void*  dst = d_in[2];
    const float* W1  = (const float*)d_in[3];
    const float* b1  = (const float*)d_in[4];
    const float* W2  = (const float*)d_in[5];
    const float* b2  = (const float*)d_in[6];
    const float* W3  = (const float*)d_in[7];
    const float* b3  = (const float*)d_in[8];
    float* out = (float*)d_out;

    const int N1 = in_sizes[4];          // 256
    const int N2 = in_sizes[6];          // 512
    const int N3 = in_sizes[8];          // 128
    const int K1 = in_sizes[3] / N1;     // 128
    const int M  = in_sizes[0] / K1;     // 100000
    const int E  = in_sizes[1];          // 3200000

    __half *xh, *h1, *h2, *hh, *w1, *w2, *w3;
    cudaGetSymbolAddress((void**)&xh, g_xh);
    cudaGetSymbolAddress((void**)&h1, g_h1);
    cudaGetSymbolAddress((void**)&h2, g_h2);
    cudaGetSymbolAddress((void**)&hh, g_hh);
    cudaGetSymbolAddress((void**)&w1, g_w1);
    cudaGetSymbolAddress((void**)&w2, g_w2);
    cudaGetSymbolAddress((void**)&w3, g_w3);

    const int MT = (M + BM - 1) / BM;

    detect_kernel<<<1, 1>>>((const unsigned*)src);

    f2h_kernel<<<(M * K1 / 4 + 255) / 256, 256>>>(X,  xh, M * K1);
    f2h_kernel<<<(K1 * N1 / 4 + 255) / 256, 256>>>(W1, w1, K1 * N1);
    f2h_kernel<<<(N1 * N2 / 4 + 255) / 256, 256>>>(W2, w2, N1 * N2);
    f2h_kernel<<<(N2 * N3 / 4 + 255) / 256, 256>>>(W3, w3, N2 * N3);

    gemm_bias_kernel<true,  false><<<dim3(N1 / BN, MT), NTHREADS>>>(xh, w1, b1, h1, nullptr, M, K1, N1);
    gemm_bias_kernel<true,  false><<<dim3(N2 / BN, MT), NTHREADS>>>(h1, w2, b2, h2, nullptr, M, N1, N2);
    gemm_bias_kernel<false, true ><<<dim3(N3 / BN, MT), NTHREADS>>>(h2, w3, b3, hh, out,     M, N2, N3);

    const int blocks = (E + 7) / 8;      // 8 warps per 256-thread block, 1 edge/warp
    edge_kernel<<<blocks, NTHREADS>>>(src, dst, hh, out, E);
}

// round 4
// speedup vs baseline: 3.5243x; 1.5909x over previous
#include <cuda_runtime.h>
#include <cuda_fp16.h>
#include <cstdint>

// ---------------------------------------------------------------------------
// WLSMLPLayer: h = MLP(X) [3-layer, ReLU], agg[d] = sum h[src],
// out = concat([h, agg]).
// R4: fp16 mma GEMMs (unchanged) + atomic-free edge phase via on-device CSR:
//     histogram -> scan -> scatter -> per-dst register aggregation.
// ---------------------------------------------------------------------------

#define BM 128
#define BN 128
#define BK 32
#define NTHREADS 256

#define AS_STRIDE 40                 // halves per A smem row (32 + 8 pad -> 80B)
#define BS_STRIDE 136                // halves per B smem row (128 + 8 pad -> 272B)
#define A_STAGE   (BM * AS_STRIDE)
#define B_STAGE   (BK * BS_STRIDE)
#define STAGE     (A_STAGE + B_STAGE)

#define MAX_N 100000
#define MAX_E 3200000
#define CHUNK 1024
#define NCHUNK ((MAX_N + CHUNK - 1) / CHUNK)   // 98

// Scratch (device globals: allocation-free rule)
__device__ __half g_xh[MAX_N * 128];
__device__ __half g_h1[MAX_N * 256];
__device__ __half g_h2[MAX_N * 512];
__device__ __half g_hh[MAX_N * 128];
__device__ __half g_w1[128 * 256];
__device__ __half g_w2[256 * 512];
__device__ __half g_w3[512 * 128];
__device__ int    g_counts [MAX_N];
__device__ int    g_offsets[MAX_N + 1];
__device__ int    g_cursor [MAX_N];
__device__ int    g_perm   [MAX_E];
__device__ int    g_bsum   [128];
__device__ int    g_is64;

__device__ __forceinline__ void cp16(__half* smem_dst, const __half* gmem_src, int valid_bytes) {
    unsigned s = (unsigned)__cvta_generic_to_shared(smem_dst);
    asm volatile("cp.async.cg.shared.global [%0], [%1], 16, %2;"
                 :: "r"(s), "l"(gmem_src), "r"(valid_bytes));
}
__device__ __forceinline__ void cp_commit() { asm volatile("cp.async.commit_group;"); }
template <int N>
__device__ __forceinline__ void cp_wait() { asm volatile("cp.async.wait_group %0;" :: "n"(N)); }

__device__ __forceinline__ int load_idx(const void* p, int i) {
    return g_is64 ? (int)((const long long*)p)[i] : ((const int*)p)[i];
}

// ---------------------------------------------------------------------------
// GEMM: C[M,N] = act(A @ B + bias), half in/out, fp32 accum.
// DUAL: also write fp32 result into out2[:,0:128] (stride 256).
// ---------------------------------------------------------------------------
template <bool RELU, bool DUAL>
__global__ __launch_bounds__(NTHREADS, 2)
void gemm_bias_kernel(const __half* __restrict__ A, const __half* __restrict__ B,
                      const float* __restrict__ bias, __half* __restrict__ C,
                      float* __restrict__ out2, int M, int K, int N)
{
    __shared__ __align__(16) __half smem[2 * STAGE];

    const int tid  = threadIdx.x;
    const int wid  = tid >> 5, lane = tid & 31;
    const int wm   = wid >> 2;
    const int wn   = wid & 3;
    const int gid  = lane >> 2;
    const int tig  = lane & 3;
    const int bm0  = blockIdx.y * BM;
    const int bn0  = blockIdx.x * BN;

    const unsigned sbase = (unsigned)__cvta_generic_to_shared(smem);

    const int a_r  = (lane & 7) + ((lane >> 3) & 1) * 8;
    const int a_k  = ((lane >> 4) & 1) * 8;
    const int b_k  = (lane & 7) + ((lane >> 3) & 1) * 8;
    const int b_n  = ((lane >> 4) & 1) * 8;

    auto issue = [&](int kk, int stage) {
        __half* As = smem + stage * STAGE;
        __half* Bs = As + A_STAGE;
#pragma unroll
        for (int i = 0; i < 2; i++) {
            int c   = tid + 256 * i;
            int row = c >> 2, col = (c & 3) * 8;
            int r   = bm0 + row;
            int ok  = (r < M) ? 16 : 0;
            cp16(As + row * AS_STRIDE + col,
                 A + (size_t)(ok ? r : 0) * K + kk + col, ok);
        }
#pragma unroll
        for (int i = 0; i < 2; i++) {
            int c   = tid + 256 * i;
            int row = c >> 4, col = (c & 15) * 8;
            cp16(Bs + row * BS_STRIDE + col,
                 B + (size_t)(kk + row) * N + bn0 + col, 16);
        }
        cp_commit();
    };

    float acc[4][4][4];
#pragma unroll
    for (int a = 0; a < 4; a++)
#pragma unroll
        for (int b = 0; b < 4; b++)
#pragma unroll
            for (int c = 0; c < 4; c++) acc[a][b][c] = 0.f;

    const int KT = K / BK;
    issue(0, 0);

    for (int kt = 0; kt < KT; ++kt) {
        if (kt + 1 < KT) { issue((kt + 1) * BK, (kt + 1) & 1); cp_wait<1>(); }
        else             { cp_wait<0>(); }
        __syncthreads();

        const unsigned as0 = sbase + ((kt & 1) * STAGE) * 2;
        const unsigned bs0 = as0 + A_STAGE * 2;

#pragma unroll
        for (int ks = 0; ks < 2; ++ks) {
            const int k0 = ks * 16;
            unsigned af[4][4], bf[4][2];
#pragma unroll
            for (int mt = 0; mt < 4; ++mt) {
                unsigned addr = as0 + ((wm * 64 + mt * 16 + a_r) * AS_STRIDE + k0 + a_k) * 2;
                asm volatile("ldmatrix.sync.aligned.m8n8.x4.shared.b16 {%0,%1,%2,%3}, [%4];"
                             : "=r"(af[mt][0]), "=r"(af[mt][1]), "=r"(af[mt][2]), "=r"(af[mt][3])
                             : "r"(addr));
            }
#pragma unroll
            for (int np = 0; np < 2; ++np) {
                unsigned addr = bs0 + ((k0 + b_k) * BS_STRIDE + wn * 32 + np * 16 + b_n) * 2;
                asm volatile("ldmatrix.sync.aligned.m8n8.x4.trans.shared.b16 {%0,%1,%2,%3}, [%4];"
                             : "=r"(bf[2 * np][0]), "=r"(bf[2 * np][1]),
                               "=r"(bf[2 * np + 1][0]), "=r"(bf[2 * np + 1][1])
                             : "r"(addr));
            }
#pragma unroll
            for (int mt = 0; mt < 4; ++mt)
#pragma unroll
                for (int nt = 0; nt < 4; ++nt)
                    asm volatile(
                        "mma.sync.aligned.m16n8k16.row.col.f32.f16.f16.f32 "
                        "{%0,%1,%2,%3}, {%4,%5,%6,%7}, {%8,%9}, {%0,%1,%2,%3};"
                        : "+f"(acc[mt][nt][0]), "+f"(acc[mt][nt][1]),
                          "+f"(acc[mt][nt][2]), "+f"(acc[mt][nt][3])
                        : "r"(af[mt][0]), "r"(af[mt][1]), "r"(af[mt][2]), "r"(af[mt][3]),
                          "r"(bf[nt][0]), "r"(bf[nt][1]));
        }
        __syncthreads();
    }

#pragma unroll
    for (int mt = 0; mt < 4; ++mt) {
#pragma unroll
        for (int nt = 0; nt < 4; ++nt) {
            int c = bn0 + wn * 32 + nt * 8 + 2 * tig;
            float bv0 = bias[c], bv1 = bias[c + 1];
#pragma unroll
            for (int hh = 0; hh < 2; ++hh) {
                int r = bm0 + wm * 64 + mt * 16 + gid + hh * 8;
                if (r < M) {
                    float v0 = acc[mt][nt][hh * 2 + 0] + bv0;
                    float v1 = acc[mt][nt][hh * 2 + 1] + bv1;
                    if (RELU) { v0 = fmaxf(v0, 0.f); v1 = fmaxf(v1, 0.f); }
                    *reinterpret_cast<__half2*>(C + (size_t)r * N + c) =
                        __floats2half2_rn(v0, v1);
                    if (DUAL) {
                        float* orow = out2 + (size_t)r * 256;
                        orow[c    ] = v0;
                        orow[c + 1] = v1;
                    }
                }
            }
        }
    }
}

// ---------------------------------------------------------------------------
// helpers
// ---------------------------------------------------------------------------
__global__ void f2h_kernel(const float* __restrict__ in, __half* __restrict__ out, int n) {
    int idx = (blockIdx.x * blockDim.x + threadIdx.x) * 4;
    if (idx < n) {
        float4 v = *reinterpret_cast<const float4*>(in + idx);
        __half2* o = reinterpret_cast<__half2*>(out + idx);
        o[0] = __floats2half2_rn(v.x, v.y);
        o[1] = __floats2half2_rn(v.z, v.w);
    }
}

__global__ void detect_kernel(const unsigned* __restrict__ w) {
    if (threadIdx.x == 0 && blockIdx.x == 0) {
        int ok = 1;
        for (int i = 1; i < 256; i += 2) ok &= (w[i] == 0u);
        g_is64 = ok;
    }
}

// ---------------------------------------------------------------------------
// CSR build: histogram -> chunked exclusive scan -> scatter
// ---------------------------------------------------------------------------
__global__ void hist_kernel(const void* __restrict__ dstp, int* __restrict__ counts, int E) {
    int i = blockIdx.x * blockDim.x + threadIdx.x;
    if (i >= E) return;
    atomicAdd(&counts[load_idx(dstp, i)], 1);   // no return use -> RED
}

__global__ void chunk_reduce(const int* __restrict__ counts, int* __restrict__ bsum, int n) {
    __shared__ int sh[256];
    int base = blockIdx.x * CHUNK;
    int s = 0;
    for (int j = threadIdx.x; j < CHUNK; j += 256) {
        int idx = base + j;
        if (idx < n) s += counts[idx];
    }
    sh[threadIdx.x] = s;
    __syncthreads();
    for (int off = 128; off > 0; off >>= 1) {
        if (threadIdx.x < off) sh[threadIdx.x] += sh[threadIdx.x + off];
        __syncthreads();
    }
    if (threadIdx.x == 0) bsum[blockIdx.x] = sh[0];
}

__global__ void scan_partials(int* __restrict__ bsum, int nb) {
    __shared__ int sh[128];
    int t = threadIdx.x;
    int v = (t < nb) ? bsum[t] : 0;
    int orig = v;
#pragma unroll
    for (int off = 1; off < 128; off <<= 1) {
        sh[t] = v;
        __syncthreads();
        int add = (t >= off) ? sh[t - off] : 0;
        __syncthreads();
        v += add;
    }
    if (t < nb) bsum[t] = v - orig;   // exclusive
}

__global__ void chunk_scan(const int* __restrict__ counts, const int* __restrict__ bsum,
                           int* __restrict__ offsets, int n, int E) {
    __shared__ int sh[CHUNK];
    int t = threadIdx.x;
    int g = blockIdx.x * CHUNK + t;
    int v = (g < n) ? counts[g] : 0;
    int orig = v;
#pragma unroll
    for (int off = 1; off < CHUNK; off <<= 1) {
        sh[t] = v;
        __syncthreads();
        int add = (t >= off) ? sh[t - off] : 0;
        __syncthreads();
        v += add;
    }
    if (g < n) offsets[g] = v - orig + bsum[blockIdx.x];
    if (blockIdx.x == 0 && t == 0) offsets[n] = E;
}

__global__ void scatter_kernel(const void* __restrict__ srcp, const void* __restrict__ dstp,
                               int* __restrict__ cursor, int* __restrict__ perm, int E) {
    int i = blockIdx.x * blockDim.x + threadIdx.x;
    if (i >= E) return;
    int s = load_idx(srcp, i);
    int d = load_idx(dstp, i);
    int pos = atomicAdd(&cursor[d], 1);
    perm[pos] = s;
}

// ---------------------------------------------------------------------------
// Aggregation: one warp per dst node, fp32 register accumulation, no atomics.
// lane handles 4 features (uint2 of fp16 per gather).
// ---------------------------------------------------------------------------
__global__ void agg_kernel(const int* __restrict__ offsets, const int* __restrict__ perm,
                           const __half* __restrict__ hh, float* __restrict__ out, int M)
{
    int warp = (int)((blockIdx.x * (unsigned)blockDim.x + threadIdx.x) >> 5);
    int lane = threadIdx.x & 31;
    if (warp >= M) return;

    int e0 = offsets[warp];
    const int e1 = offsets[warp + 1];

    float a0 = 0.f, a1 = 0.f, a2 = 0.f, a3 = 0.f;

    while (e0 + 32 <= e1) {
        int idx = perm[e0 + lane];
#pragma unroll
        for (int j = 0; j < 32; ++j) {
            int s = __shfl_sync(0xffffffffu, idx, j);
            uint2 raw = *reinterpret_cast<const uint2*>(hh + (size_t)s * 128 + lane * 4);
            float2 f0 = __half22float2(*reinterpret_cast<__half2*>(&raw.x));
            float2 f1 = __half22float2(*reinterpret_cast<__half2*>(&raw.y));
            a0 += f0.x; a1 += f0.y; a2 += f1.x; a3 += f1.y;
        }
        e0 += 32;
    }
    int rem = e1 - e0;
    if (rem > 0) {
        int idx = (lane < rem) ? perm[e0 + lane] : 0;
        for (int j = 0; j < rem; ++j) {
            int s = __shfl_sync(0xffffffffu, idx, j);
            uint2 raw = *reinterpret_cast<const uint2*>(hh + (size_t)s * 128 + lane * 4);
            float2 f0 = __half22float2(*reinterpret_cast<__half2*>(&raw.x));
            float2 f1 = __half22float2(*reinterpret_cast<__half2*>(&raw.y));
            a0 += f0.x; a1 += f0.y; a2 += f1.x; a3 += f1.y;
        }
    }

    float4 v = make_float4(a0, a1, a2, a3);
    *reinterpret_cast<float4*>(out + (size_t)warp * 256 + 128 + lane * 4) = v;
}

// ---------------------------------------------------------------------------
extern "C" void kernel_launch(void* const* d_in, const int* in_sizes, int n_in,
                              void* d_out, int out_size)
{
    const float* X   = (const float*)d_in[0];
    const void*  src = d_in[1];
    const void*  dst = d_in[2];
    const float* W1  = (const float*)d_in[3];
    const float* b1  = (const float*)d_in[4];
    const float* W2  = (const float*)d_in[5];
    const float* b2  = (const float*)d_in[6];
    const float* W3  = (const float*)d_in[7];
    const float* b3  = (const float*)d_in[8];
    float* out = (float*)d_out;

    const int N1 = in_sizes[4];          // 256
    const int N2 = in_sizes[6];          // 512
    const int N3 = in_sizes[8];          // 128
    const int K1 = in_sizes[3] / N1;     // 128
    const int M  = in_sizes[0] / K1;     // 100000
    const int E  = in_sizes[1];          // 3200000

    __half *xh, *h1, *h2, *hh, *w1, *w2, *w3;
    int *counts, *offsets, *cursor, *perm, *bsum;
    cudaGetSymbolAddress((void**)&xh, g_xh);
    cudaGetSymbolAddress((void**)&h1, g_h1);
    cudaGetSymbolAddress((void**)&h2, g_h2);
    cudaGetSymbolAddress((void**)&hh, g_hh);
    cudaGetSymbolAddress((void**)&w1, g_w1);
    cudaGetSymbolAddress((void**)&w2, g_w2);
    cudaGetSymbolAddress((void**)&w3, g_w3);
    cudaGetSymbolAddress((void**)&counts,  g_counts);
    cudaGetSymbolAddress((void**)&offsets, g_offsets);
    cudaGetSymbolAddress((void**)&cursor,  g_cursor);
    cudaGetSymbolAddress((void**)&perm,    g_perm);
    cudaGetSymbolAddress((void**)&bsum,    g_bsum);

    const int MT = (M + BM - 1) / BM;
    const int nb = (M + CHUNK - 1) / CHUNK;
    const int EB = (E + 255) / 256;

    detect_kernel<<<1, 1>>>((const unsigned*)src);

    // --- CSR build (independent of GEMMs) ---
    cudaMemsetAsync(counts, 0, (size_t)M * sizeof(int));
    hist_kernel   <<<EB, 256>>>(dst, counts, E);
    chunk_reduce  <<<nb, 256>>>(counts, bsum, M);
    scan_partials <<<1, 128>>>(bsum, nb);
    chunk_scan    <<<nb, CHUNK>>>(counts, bsum, offsets, M, E);
    cudaMemcpyAsync(cursor, offsets, (size_t)M * sizeof(int), cudaMemcpyDeviceToDevice);
    scatter_kernel<<<EB, 256>>>(src, dst, cursor, perm, E);

    // --- MLP ---
    f2h_kernel<<<(M * K1 / 4 + 255) / 256, 256>>>(X,  xh, M * K1);
    f2h_kernel<<<(K1 * N1 / 4 + 255) / 256, 256>>>(W1, w1, K1 * N1);
    f2h_kernel<<<(N1 * N2 / 4 + 255) / 256, 256>>>(W2, w2, N1 * N2);
    f2h_kernel<<<(N2 * N3 / 4 + 255) / 256, 256>>>(W3, w3, N2 * N3);

    gemm_bias_kernel<true,  false><<<dim3(N1 / BN, MT), NTHREADS>>>(xh, w1, b1, h1, nullptr, M, K1, N1);
    gemm_bias_kernel<true,  false><<<dim3(N2 / BN, MT), NTHREADS>>>(h1, w2, b2, h2, nullptr, M, N1, N2);
    gemm_bias_kernel<false, true ><<<dim3(N3 / BN, MT), NTHREADS>>>(h2, w3, b3, hh, out,     M, N2, N3);

    // --- Aggregation (atomic-free) ---
    agg_kernel<<<(M + 7) / 8, 256>>>(offsets, perm, hh, out, M);
}

// round 6
// speedup vs baseline: 3.7762x; 1.0715x over previous
#include <cuda_runtime.h>
#include <cuda_fp16.h>
#include <cstdint>

// ---------------------------------------------------------------------------
// WLSMLPLayer: h = MLP(X) [3-layer, ReLU], agg[d] = sum h[src],
// out = concat([h, agg]).
// R6: fp16 mma.sync GEMM w/ 3-stage cp.async pipeline + CSR edge phase
//     overlapped on a side stream (fork-join, graph-captured).
// ---------------------------------------------------------------------------

#define BM 128
#define BN 128
#define BK 32
#define NTHREADS 256
#define NSTAGE 3

#define AS_STRIDE 40                 // halves per A smem row (32 + 8 pad -> 80B)
#define BS_STRIDE 136                // halves per B smem row (128 + 8 pad -> 272B)
#define A_STAGE   (BM * AS_STRIDE)   // 5120 halves
#define B_STAGE   (BK * BS_STRIDE)   // 4352 halves
#define STAGE     (A_STAGE + B_STAGE)
#define SMEM_BYTES (NSTAGE * STAGE * 2)   // 56832 B

#define MAX_N 100000
#define MAX_E 3200000
#define CHUNK 1024

// Scratch (device globals: allocation-free rule)
__device__ __half g_xh[MAX_N * 128];
__device__ __half g_h1[MAX_N * 256];
__device__ __half g_h2[MAX_N * 512];
__device__ __half g_hh[MAX_N * 128];
__device__ __half g_w1[128 * 256];
__device__ __half g_w2[256 * 512];
__device__ __half g_w3[512 * 128];
__device__ int    g_counts [MAX_N];
__device__ int    g_offsets[MAX_N + 1];
__device__ int    g_cursor [MAX_N];
__device__ int    g_perm   [MAX_E];
__device__ int    g_bsum   [128];
__device__ int    g_is64;

__device__ __forceinline__ void cp16(__half* smem_dst, const __half* gmem_src, int valid_bytes) {
    unsigned s = (unsigned)__cvta_generic_to_shared(smem_dst);
    asm volatile("cp.async.cg.shared.global [%0], [%1], 16, %2;"
                 :: "r"(s), "l"(gmem_src), "r"(valid_bytes));
}
__device__ __forceinline__ void cp_commit() { asm volatile("cp.async.commit_group;"); }
template <int N>
__device__ __forceinline__ void cp_wait() { asm volatile("cp.async.wait_group %0;" :: "n"(N)); }

__device__ __forceinline__ int load_idx(const void* p, int i) {
    return g_is64 ? (int)((const long long*)p)[i] : ((const int*)p)[i];
}

// ---------------------------------------------------------------------------
// GEMM: C[M,N] = act(A @ B + bias), half in/out, fp32 accum. 3-stage pipeline.
// DUAL: also write fp32 result into out2[:,0:128] (stride 256).
// ---------------------------------------------------------------------------
template <bool RELU, bool DUAL>
__global__ __launch_bounds__(NTHREADS, 2)
void gemm_bias_kernel(const __half* __restrict__ A, const __half* __restrict__ B,
                      const float* __restrict__ bias, __half* __restrict__ C,
                      float* __restrict__ out2, int M, int K, int N)
{
    extern __shared__ __align__(16) __half smem[];

    const int tid  = threadIdx.x;
    const int wid  = tid >> 5, lane = tid & 31;
    const int wm   = wid >> 2;
    const int wn   = wid & 3;
    const int gid  = lane >> 2;
    const int tig  = lane & 3;
    const int bm0  = blockIdx.y * BM;
    const int bn0  = blockIdx.x * BN;

    const unsigned sbase = (unsigned)__cvta_generic_to_shared(smem);

    const int a_r  = (lane & 7) + ((lane >> 3) & 1) * 8;
    const int a_k  = ((lane >> 4) & 1) * 8;
    const int b_k  = (lane & 7) + ((lane >> 3) & 1) * 8;
    const int b_n  = ((lane >> 4) & 1) * 8;

    auto issue = [&](int kt) {
        __half* As = smem + (kt % NSTAGE) * STAGE;
        __half* Bs = As + A_STAGE;
        const int kk = kt * BK;
#pragma unroll
        for (int i = 0; i < 2; i++) {
            int c   = tid + 256 * i;
            int row = c >> 2, col = (c & 3) * 8;
            int r   = bm0 + row;
            int ok  = (r < M) ? 16 : 0;
            cp16(As + row * AS_STRIDE + col,
                 A + (size_t)(ok ? r : 0) * K + kk + col, ok);
        }
#pragma unroll
        for (int i = 0; i < 2; i++) {
            int c   = tid + 256 * i;
            int row = c >> 4, col = (c & 15) * 8;
            cp16(Bs + row * BS_STRIDE + col,
                 B + (size_t)(kk + row) * N + bn0 + col, 16);
        }
        cp_commit();
    };

    float acc[4][4][4];
#pragma unroll
    for (int a = 0; a < 4; a++)
#pragma unroll
        for (int b = 0; b < 4; b++)
#pragma unroll
            for (int c = 0; c < 4; c++) acc[a][b][c] = 0.f;

    const int KT = K / BK;       // >= 4 for all three layers
    issue(0);
    issue(1);

    for (int kt = 0; kt < KT; ++kt) {
        if (kt + 2 < KT) issue(kt + 2);
        else             cp_commit();          // keep group count uniform
        cp_wait<2>();                          // stage kt resident
        __syncthreads();

        const unsigned as0 = sbase + ((kt % NSTAGE) * STAGE) * 2;
        const unsigned bs0 = as0 + A_STAGE * 2;

#pragma unroll
        for (int ks = 0; ks < 2; ++ks) {
            const int k0 = ks * 16;
            unsigned af[4][4], bf[4][2];
#pragma unroll
            for (int mt = 0; mt < 4; ++mt) {
                unsigned addr = as0 + ((wm * 64 + mt * 16 + a_r) * AS_STRIDE + k0 + a_k) * 2;
                asm volatile("ldmatrix.sync.aligned.m8n8.x4.shared.b16 {%0,%1,%2,%3}, [%4];"
                             : "=r"(af[mt][0]), "=r"(af[mt][1]), "=r"(af[mt][2]), "=r"(af[mt][3])
                             : "r"(addr));
            }
#pragma unroll
            for (int np = 0; np < 2; ++np) {
                unsigned addr = bs0 + ((k0 + b_k) * BS_STRIDE + wn * 32 + np * 16 + b_n) * 2;
                asm volatile("ldmatrix.sync.aligned.m8n8.x4.trans.shared.b16 {%0,%1,%2,%3}, [%4];"
                             : "=r"(bf[2 * np][0]), "=r"(bf[2 * np][1]),
                               "=r"(bf[2 * np + 1][0]), "=r"(bf[2 * np + 1][1])
                             : "r"(addr));
            }
#pragma unroll
            for (int mt = 0; mt < 4; ++mt)
#pragma unroll
                for (int nt = 0; nt < 4; ++nt)
                    asm volatile(
                        "mma.sync.aligned.m16n8k16.row.col.f32.f16.f16.f32 "
                        "{%0,%1,%2,%3}, {%4,%5,%6,%7}, {%8,%9}, {%0,%1,%2,%3};"
                        : "+f"(acc[mt][nt][0]), "+f"(acc[mt][nt][1]),
                          "+f"(acc[mt][nt][2]), "+f"(acc[mt][nt][3])
                        : "r"(af[mt][0]), "r"(af[mt][1]), "r"(af[mt][2]), "r"(af[mt][3]),
                          "r"(bf[nt][0]), "r"(bf[nt][1]));
        }
        __syncthreads();
    }

#pragma unroll
    for (int mt = 0; mt < 4; ++mt) {
#pragma unroll
        for (int nt = 0; nt < 4; ++nt) {
            int c = bn0 + wn * 32 + nt * 8 + 2 * tig;
            float bv0 = bias[c], bv1 = bias[c + 1];
#pragma unroll
            for (int hh = 0; hh < 2; ++hh) {
                int r = bm0 + wm * 64 + mt * 16 + gid + hh * 8;
                if (r < M) {
                    float v0 = acc[mt][nt][hh * 2 + 0] + bv0;
                    float v1 = acc[mt][nt][hh * 2 + 1] + bv1;
                    if (RELU) { v0 = fmaxf(v0, 0.f); v1 = fmaxf(v1, 0.f); }
                    *reinterpret_cast<__half2*>(C + (size_t)r * N + c) =
                        __floats2half2_rn(v0, v1);
                    if (DUAL) {
                        float* orow = out2 + (size_t)r * 256;
                        orow[c    ] = v0;
                        orow[c + 1] = v1;
                    }
                }
            }
        }
    }
}

// ---------------------------------------------------------------------------
// helpers
// ---------------------------------------------------------------------------
__global__ void f2h_kernel(const float* __restrict__ in, __half* __restrict__ out, int n) {
    int idx = (blockIdx.x * blockDim.x + threadIdx.x) * 4;
    if (idx < n) {
        float4 v = *reinterpret_cast<const float4*>(in + idx);
        __half2* o = reinterpret_cast<__half2*>(out + idx);
        o[0] = __floats2half2_rn(v.x, v.y);
        o[1] = __floats2half2_rn(v.z, v.w);
    }
}

__global__ void detect_kernel(const unsigned* __restrict__ w) {
    if (threadIdx.x == 0 && blockIdx.x == 0) {
        int ok = 1;
        for (int i = 1; i < 256; i += 2) ok &= (w[i] == 0u);
        g_is64 = ok;
    }
}

// ---------------------------------------------------------------------------
// CSR build: histogram -> chunked exclusive scan -> scatter
// ---------------------------------------------------------------------------
__global__ void hist_kernel(const void* __restrict__ dstp, int* __restrict__ counts, int E) {
    int i = blockIdx.x * blockDim.x + threadIdx.x;
    if (i >= E) return;
    atomicAdd(&counts[load_idx(dstp, i)], 1);
}

__global__ void chunk_reduce(const int* __restrict__ counts, int* __restrict__ bsum, int n) {
    __shared__ int sh[256];
    int base = blockIdx.x * CHUNK;
    int s = 0;
    for (int j = threadIdx.x; j < CHUNK; j += 256) {
        int idx = base + j;
        if (idx < n) s += counts[idx];
    }
    sh[threadIdx.x] = s;
    __syncthreads();
    for (int off = 128; off > 0; off >>= 1) {
        if (threadIdx.x < off) sh[threadIdx.x] += sh[threadIdx.x + off];
        __syncthreads();
    }
    if (threadIdx.x == 0) bsum[blockIdx.x] = sh[0];
}

__global__ void scan_partials(int* __restrict__ bsum, int nb) {
    __shared__ int sh[128];
    int t = threadIdx.x;
    int v = (t < nb) ? bsum[t] : 0;
    int orig = v;
#pragma unroll
    for (int off = 1; off < 128; off <<= 1) {
        sh[t] = v;
        __syncthreads();
        int add = (t >= off) ? sh[t - off] : 0;
        __syncthreads();
        v += add;
    }
    if (t < nb) bsum[t] = v - orig;
}

__global__ void chunk_scan(const int* __restrict__ counts, const int* __restrict__ bsum,
                           int* __restrict__ offsets, int n, int E) {
    __shared__ int sh[CHUNK];
    int t = threadIdx.x;
    int g = blockIdx.x * CHUNK + t;
    int v = (g < n) ? counts[g] : 0;
    int orig = v;
#pragma unroll
    for (int off = 1; off < CHUNK; off <<= 1) {
        sh[t] = v;
        __syncthreads();
        int add = (t >= off) ? sh[t - off] : 0;
        __syncthreads();
        v += add;
    }
    if (g < n) offsets[g] = v - orig + bsum[blockIdx.x];
    if (blockIdx.x == 0 && t == 0) offsets[n] = E;
}

__global__ void scatter_kernel(const void* __restrict__ srcp, const void* __restrict__ dstp,
                               int* __restrict__ cursor, int* __restrict__ perm, int E) {
    int i = blockIdx.x * blockDim.x + threadIdx.x;
    if (i >= E) return;
    int s = load_idx(srcp, i);
    int d = load_idx(dstp, i);
    int pos = atomicAdd(&cursor[d], 1);
    perm[pos] = s;
}

// ---------------------------------------------------------------------------
// Aggregation: one warp per dst node, fp32 register accumulation, no atomics.
// ---------------------------------------------------------------------------
__global__ void agg_kernel(const int* __restrict__ offsets, const int* __restrict__ perm,
                           const __half* __restrict__ hh, float* __restrict__ out, int M)
{
    int warp = (int)((blockIdx.x * (unsigned)blockDim.x + threadIdx.x) >> 5);
    int lane = threadIdx.x & 31;
    if (warp >= M) return;

    int e0 = offsets[warp];
    const int e1 = offsets[warp + 1];

    float a0 = 0.f, a1 = 0.f, a2 = 0.f, a3 = 0.f;

    while (e0 + 32 <= e1) {
        int idx = perm[e0 + lane];
#pragma unroll
        for (int j = 0; j < 32; ++j) {
            int s = __shfl_sync(0xffffffffu, idx, j);
            uint2 raw = *reinterpret_cast<const uint2*>(hh + (size_t)s * 128 + lane * 4);
            float2 f0 = __half22float2(*reinterpret_cast<__half2*>(&raw.x));
            float2 f1 = __half22float2(*reinterpret_cast<__half2*>(&raw.y));
            a0 += f0.x; a1 += f0.y; a2 += f1.x; a3 += f1.y;
        }
        e0 += 32;
    }
    int rem = e1 - e0;
    if (rem > 0) {
        int idx = (lane < rem) ? perm[e0 + lane] : 0;
        for (int j = 0; j < rem; ++j) {
            int s = __shfl_sync(0xffffffffu, idx, j);
            uint2 raw = *reinterpret_cast<const uint2*>(hh + (size_t)s * 128 + lane * 4);
            float2 f0 = __half22float2(*reinterpret_cast<__half2*>(&raw.x));
            float2 f1 = __half22float2(*reinterpret_cast<__half2*>(&raw.y));
            a0 += f0.x; a1 += f0.y; a2 += f1.x; a3 += f1.y;
        }
    }

    *reinterpret_cast<float4*>(out + (size_t)warp * 256 + 128 + lane * 4) =
        make_float4(a0, a1, a2, a3);
}

// ---------------------------------------------------------------------------
extern "C" void kernel_launch(void* const* d_in, const int* in_sizes, int n_in,
                              void* d_out, int out_size)
{
    const float* X   = (const float*)d_in[0];
    const void*  src = d_in[1];
    const void*  dst = d_in[2];
    const float* W1  = (const float*)d_in[3];
    const float* b1  = (const float*)d_in[4];
    const float* W2  = (const float*)d_in[5];
    const float* b2  = (const float*)d_in[6];
    const float* W3  = (const float*)d_in[7];
    const float* b3  = (const float*)d_in[8];
    float* out = (float*)d_out;

    const int N1 = in_sizes[4];          // 256
    const int N2 = in_sizes[6];          // 512
    const int N3 = in_sizes[8];          // 128
    const int K1 = in_sizes[3] / N1;     // 128
    const int M  = in_sizes[0] / K1;     // 100000
    const int E  = in_sizes[1];          // 3200000

    __half *xh, *h1, *h2, *hh, *w1, *w2, *w3;
    int *counts, *offsets, *cursor, *perm, *bsum;
    cudaGetSymbolAddress((void**)&xh, g_xh);
    cudaGetSymbolAddress((void**)&h1, g_h1);
    cudaGetSymbolAddress((void**)&h2, g_h2);
    cudaGetSymbolAddress((void**)&hh, g_hh);
    cudaGetSymbolAddress((void**)&w1, g_w1);
    cudaGetSymbolAddress((void**)&w2, g_w2);
    cudaGetSymbolAddress((void**)&w3, g_w3);
    cudaGetSymbolAddress((void**)&counts,  g_counts);
    cudaGetSymbolAddress((void**)&offsets, g_offsets);
    cudaGetSymbolAddress((void**)&cursor,  g_cursor);
    cudaGetSymbolAddress((void**)&perm,    g_perm);
    cudaGetSymbolAddress((void**)&bsum,    g_bsum);

    cudaFuncSetAttribute(gemm_bias_kernel<true,  false>,
                         cudaFuncAttributeMaxDynamicSharedMemorySize, SMEM_BYTES);
    cudaFuncSetAttribute(gemm_bias_kernel<false, true>,
                         cudaFuncAttributeMaxDynamicSharedMemorySize, SMEM_BYTES);

    const int MT = (M + BM - 1) / BM;
    const int nb = (M + CHUNK - 1) / CHUNK;
    const int EB = (E + 255) / 256;

    // Side stream + events for fork-join (created fresh; kernel_launch runs
    // only twice outside the graph, so no unbounded resource growth).
    cudaStream_t s2;
    cudaEvent_t ev_fork, ev_join;
    cudaStreamCreateWithFlags(&s2, cudaStreamNonBlocking);
    cudaEventCreateWithFlags(&ev_fork, cudaEventDisableTiming);
    cudaEventCreateWithFlags(&ev_join, cudaEventDisableTiming);

    detect_kernel<<<1, 1>>>((const unsigned*)src);

    // fork: CSR build on s2, concurrent with conversions + GEMMs on default
    cudaEventRecord(ev_fork, 0);
    cudaStreamWaitEvent(s2, ev_fork, 0);

    cudaMemsetAsync(counts, 0, (size_t)M * sizeof(int), s2);
    hist_kernel   <<<EB, 256, 0, s2>>>(dst, counts, E);
    chunk_reduce  <<<nb, 256, 0, s2>>>(counts, bsum, M);
    scan_partials <<<1, 128, 0, s2>>>(bsum, nb);
    chunk_scan    <<<nb, CHUNK, 0, s2>>>(counts, bsum, offsets, M, E);
    cudaMemcpyAsync(cursor, offsets, (size_t)M * sizeof(int),
                    cudaMemcpyDeviceToDevice, s2);
    scatter_kernel<<<EB, 256, 0, s2>>>(src, dst, cursor, perm, E);
    cudaEventRecord(ev_join, s2);

    // main: conversions + MLP
    f2h_kernel<<<(M * K1 / 4 + 255) / 256, 256>>>(X,  xh, M * K1);
    f2h_kernel<<<(K1 * N1 / 4 + 255) / 256, 256>>>(W1, w1, K1 * N1);
    f2h_kernel<<<(N1 * N2 / 4 + 255) / 256, 256>>>(W2, w2, N1 * N2);
    f2h_kernel<<<(N2 * N3 / 4 + 255) / 256, 256>>>(W3, w3, N2 * N3);

    gemm_bias_kernel<true,  false><<<dim3(N1 / BN, MT), NTHREADS, SMEM_BYTES>>>(xh, w1, b1, h1, nullptr, M, K1, N1);
    gemm_bias_kernel<true,  false><<<dim3(N2 / BN, MT), NTHREADS, SMEM_BYTES>>>(h1, w2, b2, h2, nullptr, M, N1, N2);
    gemm_bias_kernel<false, true ><<<dim3(N3 / BN, MT), NTHREADS, SMEM_BYTES>>>(h2, w3, b3, hh, out,     M, N2, N3);

    // join: aggregation needs both the CSR and hh
    cudaStreamWaitEvent(0, ev_join, 0);
    agg_kernel<<<(M + 7) / 8, 256>>>(offsets, perm, hh, out, M);
}

// round 7
// speedup vs baseline: 3.8729x; 1.0256x over previous
#include <cuda_runtime.h>
#include <cuda_fp16.h>
#include <cstdint>

// ---------------------------------------------------------------------------
// WLSMLPLayer: h = MLP(X) [3-layer, ReLU], agg[d] = sum h[src],
// out = concat([h, agg]).
// R7: 4-stage cp.async ring w/ single barrier per k-tile; detect + weight
//     conversions moved off the critical path; CSR overlapped (fork-join).
// ---------------------------------------------------------------------------

#define BM 128
#define BN 128
#define BK 32
#define NTHREADS 256
#define NSTAGE 4

#define AS_STRIDE 40                 // halves per A smem row (32 + 8 pad -> 80B)
#define BS_STRIDE 136                // halves per B smem row (128 + 8 pad -> 272B)
#define A_STAGE   (BM * AS_STRIDE)   // 5120 halves
#define B_STAGE   (BK * BS_STRIDE)   // 4352 halves
#define STAGE     (A_STAGE + B_STAGE)
#define SMEM_BYTES (NSTAGE * STAGE * 2)   // 75776 B

#define MAX_N 100000
#define MAX_E 3200000
#define CHUNK 1024

// Scratch (device globals: allocation-free rule)
__device__ __half g_xh[MAX_N * 128];
__device__ __half g_h1[MAX_N * 256];
__device__ __half g_h2[MAX_N * 512];
__device__ __half g_hh[MAX_N * 128];
__device__ __half g_w1[128 * 256];
__device__ __half g_w2[256 * 512];
__device__ __half g_w3[512 * 128];
__device__ int    g_counts [MAX_N];
__device__ int    g_offsets[MAX_N + 1];
__device__ int    g_cursor [MAX_N];
__device__ int    g_perm   [MAX_E];
__device__ int    g_bsum   [128];
__device__ int    g_is64;

__device__ __forceinline__ void cp16(__half* smem_dst, const __half* gmem_src, int valid_bytes) {
    unsigned s = (unsigned)__cvta_generic_to_shared(smem_dst);
    asm volatile("cp.async.cg.shared.global [%0], [%1], 16, %2;"
                 :: "r"(s), "l"(gmem_src), "r"(valid_bytes));
}
__device__ __forceinline__ void cp_commit() { asm volatile("cp.async.commit_group;"); }
template <int N>
__device__ __forceinline__ void cp_wait() { asm volatile("cp.async.wait_group %0;" :: "n"(N)); }

__device__ __forceinline__ int load_idx(const void* p, int i) {
    return g_is64 ? (int)((const long long*)p)[i] : ((const int*)p)[i];
}

// ---------------------------------------------------------------------------
// GEMM: C[M,N] = act(A @ B + bias), half in/out, fp32 accum.
// 4-stage cp.async ring, ONE __syncthreads per k-tile.
// DUAL: also write fp32 result into out2[:,0:128] (stride 256).
// ---------------------------------------------------------------------------
template <bool RELU, bool DUAL>
__global__ __launch_bounds__(NTHREADS, 2)
void gemm_bias_kernel(const __half* __restrict__ A, const __half* __restrict__ B,
                      const float* __restrict__ bias, __half* __restrict__ C,
                      float* __restrict__ out2, int M, int K, int N)
{
    extern __shared__ __align__(16) __half smem[];

    const int tid  = threadIdx.x;
    const int wid  = tid >> 5, lane = tid & 31;
    const int wm   = wid >> 2;
    const int wn   = wid & 3;
    const int gid  = lane >> 2;
    const int tig  = lane & 3;
    const int bm0  = blockIdx.y * BM;
    const int bn0  = blockIdx.x * BN;

    const unsigned sbase = (unsigned)__cvta_generic_to_shared(smem);

    const int a_r  = (lane & 7) + ((lane >> 3) & 1) * 8;
    const int a_k  = ((lane >> 4) & 1) * 8;
    const int b_k  = (lane & 7) + ((lane >> 3) & 1) * 8;
    const int b_n  = ((lane >> 4) & 1) * 8;

    auto issue = [&](int kt) {
        __half* As = smem + (kt % NSTAGE) * STAGE;
        __half* Bs = As + A_STAGE;
        const int kk = kt * BK;
#pragma unroll
        for (int i = 0; i < 2; i++) {
            int c   = tid + 256 * i;
            int row = c >> 2, col = (c & 3) * 8;
            int r   = bm0 + row;
            int ok  = (r < M) ? 16 : 0;
            cp16(As + row * AS_STRIDE + col,
                 A + (size_t)(ok ? r : 0) * K + kk + col, ok);
        }
#pragma unroll
        for (int i = 0; i < 2; i++) {
            int c   = tid + 256 * i;
            int row = c >> 4, col = (c & 15) * 8;
            cp16(Bs + row * BS_STRIDE + col,
                 B + (size_t)(kk + row) * N + bn0 + col, 16);
        }
        cp_commit();
    };

    float acc[4][4][4];
#pragma unroll
    for (int a = 0; a < 4; a++)
#pragma unroll
        for (int b = 0; b < 4; b++)
#pragma unroll
            for (int c = 0; c < 4; c++) acc[a][b][c] = 0.f;

    const int KT = K / BK;       // 4 / 8 / 16
    issue(0);
    issue(1);
    issue(2);

    for (int kt = 0; kt < KT; ++kt) {
        cp_wait<2>();                          // stage kt data arrived (this thread)
        __syncthreads();                       // ... and for all threads; also
                                               // proves all warps done with kt-1
        if (kt + 3 < KT) issue(kt + 3);        // rewrites stage consumed at kt-1
        else             cp_commit();          // keep group count uniform

        const unsigned as0 = sbase + ((kt % NSTAGE) * STAGE) * 2;
        const unsigned bs0 = as0 + A_STAGE * 2;

#pragma unroll
        for (int ks = 0; ks < 2; ++ks) {
            const int k0 = ks * 16;
            unsigned af[4][4], bf[4][2];
#pragma unroll
            for (int mt = 0; mt < 4; ++mt) {
                unsigned addr = as0 + ((wm * 64 + mt * 16 + a_r) * AS_STRIDE + k0 + a_k) * 2;
                asm volatile("ldmatrix.sync.aligned.m8n8.x4.shared.b16 {%0,%1,%2,%3}, [%4];"
                             : "=r"(af[mt][0]), "=r"(af[mt][1]), "=r"(af[mt][2]), "=r"(af[mt][3])
                             : "r"(addr));
            }
#pragma unroll
            for (int np = 0; np < 2; ++np) {
                unsigned addr = bs0 + ((k0 + b_k) * BS_STRIDE + wn * 32 + np * 16 + b_n) * 2;
                asm volatile("ldmatrix.sync.aligned.m8n8.x4.trans.shared.b16 {%0,%1,%2,%3}, [%4];"
                             : "=r"(bf[2 * np][0]), "=r"(bf[2 * np][1]),
                               "=r"(bf[2 * np + 1][0]), "=r"(bf[2 * np + 1][1])
                             : "r"(addr));
            }
#pragma unroll
            for (int mt = 0; mt < 4; ++mt)
#pragma unroll
                for (int nt = 0; nt < 4; ++nt)
                    asm volatile(
                        "mma.sync.aligned.m16n8k16.row.col.f32.f16.f16.f32 "
                        "{%0,%1,%2,%3}, {%4,%5,%6,%7}, {%8,%9}, {%0,%1,%2,%3};"
                        : "+f"(acc[mt][nt][0]), "+f"(acc[mt][nt][1]),
                          "+f"(acc[mt][nt][2]), "+f"(acc[mt][nt][3])
                        : "r"(af[mt][0]), "r"(af[mt][1]), "r"(af[mt][2]), "r"(af[mt][3]),
                          "r"(bf[nt][0]), "r"(bf[nt][1]));
        }
    }

#pragma unroll
    for (int mt = 0; mt < 4; ++mt) {
#pragma unroll
        for (int nt = 0; nt < 4; ++nt) {
            int c = bn0 + wn * 32 + nt * 8 + 2 * tig;
            float bv0 = bias[c], bv1 = bias[c + 1];
#pragma unroll
            for (int hh = 0; hh < 2; ++hh) {
                int r = bm0 + wm * 64 + mt * 16 + gid + hh * 8;
                if (r < M) {
                    float v0 = acc[mt][nt][hh * 2 + 0] + bv0;
                    float v1 = acc[mt][nt][hh * 2 + 1] + bv1;
                    if (RELU) { v0 = fmaxf(v0, 0.f); v1 = fmaxf(v1, 0.f); }
                    *reinterpret_cast<__half2*>(C + (size_t)r * N + c) =
                        __floats2half2_rn(v0, v1);
                    if (DUAL) {
                        float* orow = out2 + (size_t)r * 256;
                        orow[c    ] = v0;
                        orow[c + 1] = v1;
                    }
                }
            }
        }
    }
}

// ---------------------------------------------------------------------------
// helpers
// ---------------------------------------------------------------------------
__global__ void f2h_kernel(const float* __restrict__ in, __half* __restrict__ out, int n) {
    int idx = (blockIdx.x * blockDim.x + threadIdx.x) * 4;
    if (idx < n) {
        float4 v = *reinterpret_cast<const float4*>(in + idx);
        __half2* o = reinterpret_cast<__half2*>(out + idx);
        o[0] = __floats2half2_rn(v.x, v.y);
        o[1] = __floats2half2_rn(v.z, v.w);
    }
}

__global__ void detect_kernel(const unsigned* __restrict__ w) {
    if (threadIdx.x == 0 && blockIdx.x == 0) {
        int ok = 1;
        for (int i = 1; i < 256; i += 2) ok &= (w[i] == 0u);
        g_is64 = ok;
    }
}

// ---------------------------------------------------------------------------
// CSR build: histogram -> chunked exclusive scan -> scatter
// ---------------------------------------------------------------------------
__global__ void hist_kernel(const void* __restrict__ dstp, int* __restrict__ counts, int E) {
    int i = blockIdx.x * blockDim.x + threadIdx.x;
    if (i >= E) return;
    atomicAdd(&counts[load_idx(dstp, i)], 1);
}

__global__ void chunk_reduce(const int* __restrict__ counts, int* __restrict__ bsum, int n) {
    __shared__ int sh[256];
    int base = blockIdx.x * CHUNK;
    int s = 0;
    for (int j = threadIdx.x; j < CHUNK; j += 256) {
        int idx = base + j;
        if (idx < n) s += counts[idx];
    }
    sh[threadIdx.x] = s;
    __syncthreads();
    for (int off = 128; off > 0; off >>= 1) {
        if (threadIdx.x < off) sh[threadIdx.x] += sh[threadIdx.x + off];
        __syncthreads();
    }
    if (threadIdx.x == 0) bsum[blockIdx.x] = sh[0];
}

__global__ void scan_partials(int* __restrict__ bsum, int nb) {
    __shared__ int sh[128];
    int t = threadIdx.x;
    int v = (t < nb) ? bsum[t] : 0;
    int orig = v;
#pragma unroll
    for (int off = 1; off < 128; off <<= 1) {
        sh[t] = v;
        __syncthreads();
        int add = (t >= off) ? sh[t - off] : 0;
        __syncthreads();
        v += add;
    }
    if (t < nb) bsum[t] = v - orig;
}

__global__ void chunk_scan(const int* __restrict__ counts, const int* __restrict__ bsum,
                           int* __restrict__ offsets, int n, int E) {
    __shared__ int sh[CHUNK];
    int t = threadIdx.x;
    int g = blockIdx.x * CHUNK + t;
    int v = (g < n) ? counts[g] : 0;
    int orig = v;
#pragma unroll
    for (int off = 1; off < CHUNK; off <<= 1) {
        sh[t] = v;
        __syncthreads();
        int add = (t >= off) ? sh[t - off] : 0;
        __syncthreads();
        v += add;
    }
    if (g < n) offsets[g] = v - orig + bsum[blockIdx.x];
    if (blockIdx.x == 0 && t == 0) offsets[n] = E;
}

__global__ void scatter_kernel(const void* __restrict__ srcp, const void* __restrict__ dstp,
                               int* __restrict__ cursor, int* __restrict__ perm, int E) {
    int i = blockIdx.x * blockDim.x + threadIdx.x;
    if (i >= E) return;
    int s = load_idx(srcp, i);
    int d = load_idx(dstp, i);
    int pos = atomicAdd(&cursor[d], 1);
    perm[pos] = s;
}

// ---------------------------------------------------------------------------
// Aggregation: one warp per dst node, fp32 register accumulation, no atomics.
// ---------------------------------------------------------------------------
__global__ void agg_kernel(const int* __restrict__ offsets, const int* __restrict__ perm,
                           const __half* __restrict__ hh, float* __restrict__ out, int M)
{
    int warp = (int)((blockIdx.x * (unsigned)blockDim.x + threadIdx.x) >> 5);
    int lane = threadIdx.x & 31;
    if (warp >= M) return;

    int e0 = offsets[warp];
    const int e1 = offsets[warp + 1];

    float a0 = 0.f, a1 = 0.f, a2 = 0.f, a3 = 0.f;

    while (e0 + 32 <= e1) {
        int idx = perm[e0 + lane];
#pragma unroll
        for (int j = 0; j < 32; ++j) {
            int s = __shfl_sync(0xffffffffu, idx, j);
            uint2 raw = *reinterpret_cast<const uint2*>(hh + (size_t)s * 128 + lane * 4);
            float2 f0 = __half22float2(*reinterpret_cast<__half2*>(&raw.x));
            float2 f1 = __half22float2(*reinterpret_cast<__half2*>(&raw.y));
            a0 += f0.x; a1 += f0.y; a2 += f1.x; a3 += f1.y;
        }
        e0 += 32;
    }
    int rem = e1 - e0;
    if (rem > 0) {
        int idx = (lane < rem) ? perm[e0 + lane] : 0;
        for (int j = 0; j < rem; ++j) {
            int s = __shfl_sync(0xffffffffu, idx, j);
            uint2 raw = *reinterpret_cast<const uint2*>(hh + (size_t)s * 128 + lane * 4);
            float2 f0 = __half22float2(*reinterpret_cast<__half2*>(&raw.x));
            float2 f1 = __half22float2(*reinterpret_cast<__half2*>(&raw.y));
            a0 += f0.x; a1 += f0.y; a2 += f1.x; a3 += f1.y;
        }
    }

    *reinterpret_cast<float4*>(out + (size_t)warp * 256 + 128 + lane * 4) =
        make_float4(a0, a1, a2, a3);
}

// ---------------------------------------------------------------------------
extern "C" void kernel_launch(void* const* d_in, const int* in_sizes, int n_in,
                              void* d_out, int out_size)
{
    const float* X   = (const float*)d_in[0];
    const void*  src = d_in[1];
    const void*  dst = d_in[2];
    const float* W1  = (const float*)d_in[3];
    const float* b1  = (const float*)d_in[4];
    const float* W2  = (const float*)d_in[5];
    const float* b2  = (const float*)d_in[6];
    const float* W3  = (const float*)d_in[7];
    const float* b3  = (const float*)d_in[8];
    float* out = (float*)d_out;

    const int N1 = in_sizes[4];          // 256
    const int N2 = in_sizes[6];          // 512
    const int N3 = in_sizes[8];          // 128
    const int K1 = in_sizes[3] / N1;     // 128
    const int M  = in_sizes[0] / K1;     // 100000
    const int E  = in_sizes[1];          // 3200000

    __half *xh, *h1, *h2, *hh, *w1, *w2, *w3;
    int *counts, *offsets, *cursor, *perm, *bsum;
    cudaGetSymbolAddress((void**)&xh, g_xh);
    cudaGetSymbolAddress((void**)&h1, g_h1);
    cudaGetSymbolAddress((void**)&h2, g_h2);
    cudaGetSymbolAddress((void**)&hh, g_hh);
    cudaGetSymbolAddress((void**)&w1, g_w1);
    cudaGetSymbolAddress((void**)&w2, g_w2);
    cudaGetSymbolAddress((void**)&w3, g_w3);
    cudaGetSymbolAddress((void**)&counts,  g_counts);
    cudaGetSymbolAddress((void**)&offsets, g_offsets);
    cudaGetSymbolAddress((void**)&cursor,  g_cursor);
    cudaGetSymbolAddress((void**)&perm,    g_perm);
    cudaGetSymbolAddress((void**)&bsum,    g_bsum);

    cudaFuncSetAttribute(gemm_bias_kernel<true,  false>,
                         cudaFuncAttributeMaxDynamicSharedMemorySize, SMEM_BYTES);
    cudaFuncSetAttribute(gemm_bias_kernel<false, true>,
                         cudaFuncAttributeMaxDynamicSharedMemorySize, SMEM_BYTES);

    const int MT = (M + BM - 1) / BM;
    const int nb = (M + CHUNK - 1) / CHUNK;
    const int EB = (E + 255) / 256;

    cudaStream_t s2;
    cudaEvent_t ev_fork, ev_w, ev_join;
    cudaStreamCreateWithFlags(&s2, cudaStreamNonBlocking);
    cudaEventCreateWithFlags(&ev_fork, cudaEventDisableTiming);
    cudaEventCreateWithFlags(&ev_w,    cudaEventDisableTiming);
    cudaEventCreateWithFlags(&ev_join, cudaEventDisableTiming);

    // fork
    cudaEventRecord(ev_fork, 0);
    cudaStreamWaitEvent(s2, ev_fork, 0);

    // side stream: weight conversions (needed by gemm1 soon) then CSR build
    f2h_kernel<<<(K1 * N1 / 4 + 255) / 256, 256, 0, s2>>>(W1, w1, K1 * N1);
    f2h_kernel<<<(N1 * N2 / 4 + 255) / 256, 256, 0, s2>>>(W2, w2, N1 * N2);
    f2h_kernel<<<(N2 * N3 / 4 + 255) / 256, 256, 0, s2>>>(W3, w3, N2 * N3);
    cudaEventRecord(ev_w, s2);

    detect_kernel <<<1, 1, 0, s2>>>((const unsigned*)src);
    cudaMemsetAsync(counts, 0, (size_t)M * sizeof(int), s2);
    hist_kernel   <<<EB, 256, 0, s2>>>(dst, counts, E);
    chunk_reduce  <<<nb, 256, 0, s2>>>(counts, bsum, M);
    scan_partials <<<1, 128, 0, s2>>>(bsum, nb);
    chunk_scan    <<<nb, CHUNK, 0, s2>>>(counts, bsum, offsets, M, E);
    cudaMemcpyAsync(cursor, offsets, (size_t)M * sizeof(int),
                    cudaMemcpyDeviceToDevice, s2);
    scatter_kernel<<<EB, 256, 0, s2>>>(src, dst, cursor, perm, E);
    cudaEventRecord(ev_join, s2);

    // main: X conversion + MLP
    f2h_kernel<<<(M * K1 / 4 + 255) / 256, 256>>>(X, xh, M * K1);
    cudaStreamWaitEvent(0, ev_w, 0);   // w1/w2/w3 ready (completes well before)

    gemm_bias_kernel<true,  false><<<dim3(N1 / BN, MT), NTHREADS, SMEM_BYTES>>>(xh, w1, b1, h1, nullptr, M, K1, N1);
    gemm_bias_kernel<true,  false><<<dim3(N2 / BN, MT), NTHREADS, SMEM_BYTES>>>(h1, w2, b2, h2, nullptr, M, N1, N2);
    gemm_bias_kernel<false, true ><<<dim3(N3 / BN, MT), NTHREADS, SMEM_BYTES>>>(h2, w3, b3, hh, out,     M, N2, N3);

    // join: aggregation needs both the CSR and hh
    cudaStreamWaitEvent(0, ev_join, 0);
    agg_kernel<<<(M + 7) / 8, 256>>>(offsets, perm, hh, out, M);
}

// round 11
// speedup vs baseline: 4.1424x; 1.0696x over previous
#include <cuda_runtime.h>
#include <cuda_fp16.h>
#include <cstdint>

// ---------------------------------------------------------------------------
// WLSMLPLayer: h = MLP(X) [3-layer, ReLU], agg[d] = sum h[src],
// out = concat([h, agg]).
// R11: FUSED MLP, fixed B-tile fill (R10 bug: issueB loaded only half of each
//      B row — stride was 16 halves but cp.async copies 8 halves). CSR edge
//      phase unchanged, overlapped on a side stream.
// ---------------------------------------------------------------------------

#define MAX_N 100000
#define MAX_E 3200000
#define CHUNK 1024

// Fused-kernel SMEM layout (halves). X aliases h2 (X dead after layer 1).
#define H1_S 264                      // 256 + 8 pad
#define H2_S 520                      // 512 + 8 pad
#define X_S  136                      // 128 + 8 pad
#define H1_OFF 0
#define H2_OFF (128 * H1_S)           // 33792
#define X_OFF  H2_OFF
#define RING_OFF (H2_OFF + 128 * H2_S)   // 100352
#define RING_H (32 * 136)             // 4352 halves per stage
#define SMEM_HALVES (RING_OFF + 2 * RING_H)   // 109056
#define FUSED_SMEM (SMEM_HALVES * 2)          // 218112 B

// Scratch (device globals: allocation-free rule)
__device__ __half g_hh[MAX_N * 128];
__device__ __half g_w1[128 * 256];
__device__ __half g_w2[256 * 512];
__device__ __half g_w3[512 * 128];
__device__ int    g_counts [MAX_N];
__device__ int    g_offsets[MAX_N + 1];
__device__ int    g_cursor [MAX_N];
__device__ int    g_perm   [MAX_E];
__device__ int    g_bsum   [128];
__device__ int    g_is64;

__device__ __forceinline__ int load_idx(const void* p, int i) {
    return g_is64 ? (int)((const long long*)p)[i] : ((const int*)p)[i];
}

// ---------------------------------------------------------------------------
// One 128x128 output tile: acc = A_smem[128, K] @ B_gmem[K, N][:, n0:n0+128]
// A from SMEM (ldmatrix, row stride AS halves), B streamed via 2-stage
// cp.async ring. B-tile = 32 rows x 128 halves = 512 x 16B chunks,
// 2 chunks per thread (mapping identical to the validated R7 kernel).
// ---------------------------------------------------------------------------
__device__ __forceinline__ void gemm_block(
    unsigned a_u32, int AS, const __half* __restrict__ B, int N, int n0, int KT,
    unsigned ring_u32, int tid, int wm, int wn,
    int a_r, int a_k, int b_k, int b_n, float acc[4][4][4])
{
#pragma unroll
    for (int a = 0; a < 4; a++)
#pragma unroll
        for (int b = 0; b < 4; b++)
#pragma unroll
            for (int c = 0; c < 4; c++) acc[a][b][c] = 0.f;

    __syncthreads();   // all prior SMEM writes (epilogues) complete everywhere

    auto issueB = [&](int kt) {
#pragma unroll
        for (int i = 0; i < 2; i++) {
            int c   = tid + 256 * i;          // 0..511 chunk id
            int row = c >> 4;                 // 0..31
            int col = (c & 15) * 8;           // halves: 0..120, 8-half (16B) chunks
            unsigned dst = ring_u32 + ((kt & 1) * RING_H + row * 136 + col) * 2;
            const __half* src = B + (size_t)(kt * 32 + row) * N + n0 + col;
            asm volatile("cp.async.cg.shared.global [%0], [%1], 16;"
                         :: "r"(dst), "l"(src) : "memory");
        }
        asm volatile("cp.async.commit_group;" ::: "memory");
    };

    issueB(0);
    for (int kt = 0; kt < KT; ++kt) {
        if (kt + 1 < KT) { issueB(kt + 1); asm volatile("cp.async.wait_group 1;" ::: "memory"); }
        else             { asm volatile("cp.async.wait_group 0;" ::: "memory"); }
        __syncthreads();                    // ring stage kt visible to all

        const unsigned bs0 = ring_u32 + ((kt & 1) * RING_H) * 2;

#pragma unroll
        for (int ks = 0; ks < 2; ++ks) {
            const int k0g = kt * 32 + ks * 16;   // k offset into A row
            const int k0  = ks * 16;             // k offset into ring tile
            unsigned af[4][4], bf[4][2];
#pragma unroll
            for (int mt = 0; mt < 4; ++mt) {
                unsigned addr = a_u32 + ((wm * 64 + mt * 16 + a_r) * AS + k0g + a_k) * 2;
                asm volatile("ldmatrix.sync.aligned.m8n8.x4.shared.b16 {%0,%1,%2,%3}, [%4];"
                             : "=r"(af[mt][0]), "=r"(af[mt][1]), "=r"(af[mt][2]), "=r"(af[mt][3])
                             : "r"(addr) : "memory");
            }
#pragma unroll
            for (int np = 0; np < 2; ++np) {
                unsigned addr = bs0 + ((k0 + b_k) * 136 + wn * 32 + np * 16 + b_n) * 2;
                asm volatile("ldmatrix.sync.aligned.m8n8.x4.trans.shared.b16 {%0,%1,%2,%3}, [%4];"
                             : "=r"(bf[2 * np][0]), "=r"(bf[2 * np][1]),
                               "=r"(bf[2 * np + 1][0]), "=r"(bf[2 * np + 1][1])
                             : "r"(addr) : "memory");
            }
#pragma unroll
            for (int mt = 0; mt < 4; ++mt)
#pragma unroll
                for (int nt = 0; nt < 4; ++nt)
                    asm volatile(
                        "mma.sync.aligned.m16n8k16.row.col.f32.f16.f16.f32 "
                        "{%0,%1,%2,%3}, {%4,%5,%6,%7}, {%8,%9}, {%0,%1,%2,%3};"
                        : "+f"(acc[mt][nt][0]), "+f"(acc[mt][nt][1]),
                          "+f"(acc[mt][nt][2]), "+f"(acc[mt][nt][3])
                        : "r"(af[mt][0]), "r"(af[mt][1]), "r"(af[mt][2]), "r"(af[mt][3]),
                          "r"(bf[nt][0]), "r"(bf[nt][1]));
        }
        __syncthreads();                    // stage kt free for rewrite
    }
}

// ---------------------------------------------------------------------------
// Fused 3-layer MLP: one CTA = 128 nodes; h1/h2 stay in SMEM.
// ---------------------------------------------------------------------------
__global__ __launch_bounds__(256, 1)
void mlp_fused(const float* __restrict__ X,
               const __half* __restrict__ w1, const float* __restrict__ b1,
               const __half* __restrict__ w2, const float* __restrict__ b2,
               const __half* __restrict__ w3, const float* __restrict__ b3,
               __half* __restrict__ hh, float* __restrict__ out, int M)
{
    extern __shared__ __align__(16) __half sh[];
    const int tid  = threadIdx.x;
    const int wid  = tid >> 5, lane = tid & 31;
    const int wm   = wid >> 2, wn = wid & 3;
    const int gid  = lane >> 2, tig = lane & 3;
    const int bm0  = blockIdx.x * 128;

    const int a_r = (lane & 7) + ((lane >> 3) & 1) * 8;
    const int a_k = ((lane >> 4) & 1) * 8;
    const int b_k = a_r;
    const int b_n = a_k;

    const unsigned base_u32 = (unsigned)__cvta_generic_to_shared(sh);
    const unsigned x_u32    = base_u32 + X_OFF  * 2;
    const unsigned h1_u32   = base_u32 + H1_OFF * 2;
    const unsigned h2_u32   = base_u32 + H2_OFF * 2;
    const unsigned ring_u32 = base_u32 + RING_OFF * 2;

    // --- zero ALL smem (pads included): no uninitialized read is possible ---
    {
        uint4* p = reinterpret_cast<uint4*>(sh);
        const int nchunk = SMEM_HALVES / 8;
        for (int i = tid; i < nchunk; i += 256)
            p[i] = make_uint4(0u, 0u, 0u, 0u);
    }
    __syncthreads();

    // --- load X tile fp32 -> fp16 into SMEM (aliases h2 region) ---
#pragma unroll
    for (int i = 0; i < 16; i++) {
        int c   = tid + 256 * i;            // 0..4095 float4 chunks
        int row = c >> 5, col = (c & 31) * 4;
        int r   = bm0 + row;
        float4 v = make_float4(0.f, 0.f, 0.f, 0.f);
        if (r < M) v = *reinterpret_cast<const float4*>(X + (size_t)r * 128 + col);
        __half* d = sh + X_OFF + row * X_S + col;
        *reinterpret_cast<__half2*>(d)     = __floats2half2_rn(v.x, v.y);
        *reinterpret_cast<__half2*>(d + 2) = __floats2half2_rn(v.z, v.w);
    }
    __syncthreads();

    float acc[4][4][4];

    // --- layer 1: h1 = relu(X @ W1 + b1)   [K=128, N=256] ---
    for (int n0 = 0; n0 < 256; n0 += 128) {
        gemm_block(x_u32, X_S, w1, 256, n0, 4, ring_u32,
                   tid, wm, wn, a_r, a_k, b_k, b_n, acc);
#pragma unroll
        for (int mt = 0; mt < 4; ++mt)
#pragma unroll
            for (int nt = 0; nt < 4; ++nt) {
                int c = wn * 32 + nt * 8 + 2 * tig;
                float bv0 = b1[n0 + c], bv1 = b1[n0 + c + 1];
#pragma unroll
                for (int hf = 0; hf < 2; ++hf) {
                    int r = wm * 64 + mt * 16 + gid + hf * 8;
                    float v0 = fmaxf(acc[mt][nt][hf * 2 + 0] + bv0, 0.f);
                    float v1 = fmaxf(acc[mt][nt][hf * 2 + 1] + bv1, 0.f);
                    *reinterpret_cast<__half2*>(sh + H1_OFF + r * H1_S + n0 + c) =
                        __floats2half2_rn(v0, v1);
                }
            }
        __syncthreads();
    }

    // --- layer 2: h2 = relu(h1 @ W2 + b2)  [K=256, N=512] (overwrites X) ---
    for (int n0 = 0; n0 < 512; n0 += 128) {
        gemm_block(h1_u32, H1_S, w2, 512, n0, 8, ring_u32,
                   tid, wm, wn, a_r, a_k, b_k, b_n, acc);
#pragma unroll
        for (int mt = 0; mt < 4; ++mt)
#pragma unroll
            for (int nt = 0; nt < 4; ++nt) {
                int c = wn * 32 + nt * 8 + 2 * tig;
                float bv0 = b2[n0 + c], bv1 = b2[n0 + c + 1];
#pragma unroll
                for (int hf = 0; hf < 2; ++hf) {
                    int r = wm * 64 + mt * 16 + gid + hf * 8;
                    float v0 = fmaxf(acc[mt][nt][hf * 2 + 0] + bv0, 0.f);
                    float v1 = fmaxf(acc[mt][nt][hf * 2 + 1] + bv1, 0.f);
                    *reinterpret_cast<__half2*>(sh + H2_OFF + r * H2_S + n0 + c) =
                        __floats2half2_rn(v0, v1);
                }
            }
        __syncthreads();
    }

    // --- layer 3: h = h2 @ W3 + b3         [K=512, N=128] -> gmem ---
    gemm_block(h2_u32, H2_S, w3, 128, 0, 16, ring_u32,
               tid, wm, wn, a_r, a_k, b_k, b_n, acc);
#pragma unroll
    for (int mt = 0; mt < 4; ++mt)
#pragma unroll
        for (int nt = 0; nt < 4; ++nt) {
            int c = wn * 32 + nt * 8 + 2 * tig;
            float bv0 = b3[c], bv1 = b3[c + 1];
#pragma unroll
            for (int hf = 0; hf < 2; ++hf) {
                int r  = wm * 64 + mt * 16 + gid + hf * 8;
                int gr = bm0 + r;
                if (gr < M) {
                    float v0 = acc[mt][nt][hf * 2 + 0] + bv0;
                    float v1 = acc[mt][nt][hf * 2 + 1] + bv1;
                    *reinterpret_cast<__half2*>(hh + (size_t)gr * 128 + c) =
                        __floats2half2_rn(v0, v1);
                    float* orow = out + (size_t)gr * 256;
                    orow[c    ] = v0;
                    orow[c + 1] = v1;
                }
            }
        }
}

// ---------------------------------------------------------------------------
// helpers
// ---------------------------------------------------------------------------
__global__ void f2h_kernel(const float* __restrict__ in, __half* __restrict__ out, int n) {
    int idx = (blockIdx.x * blockDim.x + threadIdx.x) * 4;
    if (idx < n) {
        float4 v = *reinterpret_cast<const float4*>(in + idx);
        __half2* o = reinterpret_cast<__half2*>(out + idx);
        o[0] = __floats2half2_rn(v.x, v.y);
        o[1] = __floats2half2_rn(v.z, v.w);
    }
}

__global__ void detect_kernel(const unsigned* __restrict__ w) {
    if (threadIdx.x == 0 && blockIdx.x == 0) {
        int ok = 1;
        for (int i = 1; i < 256; i += 2) ok &= (w[i] == 0u);
        g_is64 = ok;
    }
}

// ---------------------------------------------------------------------------
// CSR build: histogram -> chunked exclusive scan -> scatter
// ---------------------------------------------------------------------------
__global__ void hist_kernel(const void* __restrict__ dstp, int* __restrict__ counts, int E) {
    int i = blockIdx.x * blockDim.x + threadIdx.x;
    if (i >= E) return;
    atomicAdd(&counts[load_idx(dstp, i)], 1);
}

__global__ void chunk_reduce(const int* __restrict__ counts, int* __restrict__ bsum, int n) {
    __shared__ int sh[256];
    int base = blockIdx.x * CHUNK;
    int s = 0;
    for (int j = threadIdx.x; j < CHUNK; j += 256) {
        int idx = base + j;
        if (idx < n) s += counts[idx];
    }
    sh[threadIdx.x] = s;
    __syncthreads();
    for (int off = 128; off > 0; off >>= 1) {
        if (threadIdx.x < off) sh[threadIdx.x] += sh[threadIdx.x + off];
        __syncthreads();
    }
    if (threadIdx.x == 0) bsum[blockIdx.x] = sh[0];
}

__global__ void scan_partials(int* __restrict__ bsum, int nb) {
    __shared__ int sh[128];
    int t = threadIdx.x;
    int v = (t < nb) ? bsum[t] : 0;
    int orig = v;
#pragma unroll
    for (int off = 1; off < 128; off <<= 1) {
        sh[t] = v;
        __syncthreads();
        int add = (t >= off) ? sh[t - off] : 0;
        __syncthreads();
        v += add;
    }
    if (t < nb) bsum[t] = v - orig;
}

__global__ void chunk_scan(const int* __restrict__ counts, const int* __restrict__ bsum,
                           int* __restrict__ offsets, int n, int E) {
    __shared__ int sh[CHUNK];
    int t = threadIdx.x;
    int g = blockIdx.x * CHUNK + t;
    int v = (g < n) ? counts[g] : 0;
    int orig = v;
#pragma unroll
    for (int off = 1; off < CHUNK; off <<= 1) {
        sh[t] = v;
        __syncthreads();
        int add = (t >= off) ? sh[t - off] : 0;
        __syncthreads();
        v += add;
    }
    if (g < n) offsets[g] = v - orig + bsum[blockIdx.x];
    if (blockIdx.x == 0 && t == 0) offsets[n] = E;
}

__global__ void scatter_kernel(const void* __restrict__ srcp, const void* __restrict__ dstp,
                               int* __restrict__ cursor, int* __restrict__ perm, int E) {
    int i = blockIdx.x * blockDim.x + threadIdx.x;
    if (i >= E) return;
    int s = load_idx(srcp, i);
    int d = load_idx(dstp, i);
    int pos = atomicAdd(&cursor[d], 1);
    perm[pos] = s;
}

// ---------------------------------------------------------------------------
// Aggregation: one warp per dst node, fp32 register accumulation, no atomics.
// ---------------------------------------------------------------------------
__global__ void agg_kernel(const int* __restrict__ offsets, const int* __restrict__ perm,
                           const __half* __restrict__ hh, float* __restrict__ out, int M)
{
    int warp = (int)((blockIdx.x * (unsigned)blockDim.x + threadIdx.x) >> 5);
    int lane = threadIdx.x & 31;
    if (warp >= M) return;

    int e0 = offsets[warp];
    const int e1 = offsets[warp + 1];

    float a0 = 0.f, a1 = 0.f, a2 = 0.f, a3 = 0.f;

    while (e0 + 32 <= e1) {
        int idx = perm[e0 + lane];
#pragma unroll
        for (int j = 0; j < 32; ++j) {
            int s = __shfl_sync(0xffffffffu, idx, j);
            uint2 raw = *reinterpret_cast<const uint2*>(hh + (size_t)s * 128 + lane * 4);
            float2 f0 = __half22float2(*reinterpret_cast<__half2*>(&raw.x));
            float2 f1 = __half22float2(*reinterpret_cast<__half2*>(&raw.y));
            a0 += f0.x; a1 += f0.y; a2 += f1.x; a3 += f1.y;
        }
        e0 += 32;
    }
    int rem = e1 - e0;
    if (rem > 0) {
        int idx = (lane < rem) ? perm[e0 + lane] : 0;
        for (int j = 0; j < rem; ++j) {
            int s = __shfl_sync(0xffffffffu, idx, j);
            uint2 raw = *reinterpret_cast<const uint2*>(hh + (size_t)s * 128 + lane * 4);
            float2 f0 = __half22float2(*reinterpret_cast<__half2*>(&raw.x));
            float2 f1 = __half22float2(*reinterpret_cast<__half2*>(&raw.y));
            a0 += f0.x; a1 += f0.y; a2 += f1.x; a3 += f1.y;
        }
    }

    *reinterpret_cast<float4*>(out + (size_t)warp * 256 + 128 + lane * 4) =
        make_float4(a0, a1, a2, a3);
}

// ---------------------------------------------------------------------------
extern "C" void kernel_launch(void* const* d_in, const int* in_sizes, int n_in,
                              void* d_out, int out_size)
{
    const float* X   = (const float*)d_in[0];
    const void*  src = d_in[1];
    const void*  dst = d_in[2];
    const float* W1  = (const float*)d_in[3];
    const float* b1  = (const float*)d_in[4];
    const float* W2  = (const float*)d_in[5];
    const float* b2  = (const float*)d_in[6];
    const float* W3  = (const float*)d_in[7];
    const float* b3  = (const float*)d_in[8];
    float* out = (float*)d_out;

    const int N1 = in_sizes[4];          // 256
    const int N2 = in_sizes[6];          // 512
    const int N3 = in_sizes[8];          // 128
    const int K1 = in_sizes[3] / N1;     // 128
    const int M  = in_sizes[0] / K1;     // 100000
    const int E  = in_sizes[1];          // 3200000

    __half *hh, *w1, *w2, *w3;
    int *counts, *offsets, *cursor, *perm, *bsum;
    cudaGetSymbolAddress((void**)&hh, g_hh);
    cudaGetSymbolAddress((void**)&w1, g_w1);
    cudaGetSymbolAddress((void**)&w2, g_w2);
    cudaGetSymbolAddress((void**)&w3, g_w3);
    cudaGetSymbolAddress((void**)&counts,  g_counts);
    cudaGetSymbolAddress((void**)&offsets, g_offsets);
    cudaGetSymbolAddress((void**)&cursor,  g_cursor);
    cudaGetSymbolAddress((void**)&perm,    g_perm);
    cudaGetSymbolAddress((void**)&bsum,    g_bsum);

    cudaFuncSetAttribute(mlp_fused,
                         cudaFuncAttributeMaxDynamicSharedMemorySize, FUSED_SMEM);

    const int MT = (M + 127) / 128;
    const int nb = (M + CHUNK - 1) / CHUNK;
    const int EB = (E + 255) / 256;

    cudaStream_t s2;
    cudaEvent_t ev_fork, ev_w, ev_join;
    cudaStreamCreateWithFlags(&s2, cudaStreamNonBlocking);
    cudaEventCreateWithFlags(&ev_fork, cudaEventDisableTiming);
    cudaEventCreateWithFlags(&ev_w,    cudaEventDisableTiming);
    cudaEventCreateWithFlags(&ev_join, cudaEventDisableTiming);

    // fork
    cudaEventRecord(ev_fork, 0);
    cudaStreamWaitEvent(s2, ev_fork, 0);

    // side stream: weight conversions, then CSR build
    f2h_kernel<<<(K1 * N1 / 4 + 255) / 256, 256, 0, s2>>>(W1, w1, K1 * N1);
    f2h_kernel<<<(N1 * N2 / 4 + 255) / 256, 256, 0, s2>>>(W2, w2, N1 * N2);
    f2h_kernel<<<(N2 * N3 / 4 + 255) / 256, 256, 0, s2>>>(W3, w3, N2 * N3);
    cudaEventRecord(ev_w, s2);

    detect_kernel <<<1, 1, 0, s2>>>((const unsigned*)src);
    cudaMemsetAsync(counts, 0, (size_t)M * sizeof(int), s2);
    hist_kernel   <<<EB, 256, 0, s2>>>(dst, counts, E);
    chunk_reduce  <<<nb, 256, 0, s2>>>(counts, bsum, M);
    scan_partials <<<1, 128, 0, s2>>>(bsum, nb);
    chunk_scan    <<<nb, CHUNK, 0, s2>>>(counts, bsum, offsets, M, E);
    cudaMemcpyAsync(cursor, offsets, (size_t)M * sizeof(int),
                    cudaMemcpyDeviceToDevice, s2);
    scatter_kernel<<<EB, 256, 0, s2>>>(src, dst, cursor, perm, E);
    cudaEventRecord(ev_join, s2);

    // main: fused MLP (needs converted weights)
    cudaStreamWaitEvent(0, ev_w, 0);
    mlp_fused<<<MT, 256, FUSED_SMEM>>>(X, w1, b1, w2, b2, w3, b3, hh, out, M);

    // join: aggregation needs both the CSR and hh
    cudaStreamWaitEvent(0, ev_join, 0);
    agg_kernel<<<(M + 7) / 8, 256>>>(offsets, perm, hh, out, M);
}